// round 4
// baseline (speedup 1.0000x reference)
#include <cuda_runtime.h>
#include <math.h>

// Problem constants
#define BHW   4096
#define CCH   256
#define NBAT  4
#define NTOK  16384
#define NGRP  32
#define GELEMS (8*BHW)
#define OUT_MAIN ((size_t)NBAT*CCH*BHW)

// ---------------- scratch ----------------------------------------------------
__device__ float g_t[(size_t)NTOK*CCH];     // normalized tokens [tok, c]
__device__ float g_qkv[(size_t)NTOK*768];   // fused qkv [tok, 768]
__device__ float g_o[(size_t)NTOK*CCH];     // attn output [tok, c]
__device__ float g_y[(size_t)NTOK*CCH];     // proj output [tok, c]
__device__ float g_u[NTOK];
__device__ float g_wqkv[768*256];
__device__ float g_bqkv[768];
__device__ float g_mu[NBAT*NGRP];
__device__ float g_rs[NBAT*NGRP];

// ---------------- GroupNorm stats -------------------------------------------
__global__ void gn_stats(const float* __restrict__ x) {
    int bg = blockIdx.x;
    const float4* p = (const float4*)(x + (size_t)bg * GELEMS);
    float s = 0.f, ss = 0.f;
    for (int i = threadIdx.x; i < GELEMS/4; i += blockDim.x) {
        float4 v = p[i];
        s  += v.x + v.y + v.z + v.w;
        ss += v.x*v.x + v.y*v.y + v.z*v.z + v.w*v.w;
    }
    __shared__ float rs[8], rss[8];
    #pragma unroll
    for (int o = 16; o; o >>= 1) { s += __shfl_down_sync(~0u, s, o); ss += __shfl_down_sync(~0u, ss, o); }
    if ((threadIdx.x & 31) == 0) { rs[threadIdx.x >> 5] = s; rss[threadIdx.x >> 5] = ss; }
    __syncthreads();
    if (threadIdx.x < 32) {
        s  = (threadIdx.x < 8) ? rs[threadIdx.x]  : 0.f;
        ss = (threadIdx.x < 8) ? rss[threadIdx.x] : 0.f;
        #pragma unroll
        for (int o = 4; o; o >>= 1) { s += __shfl_down_sync(~0u, s, o); ss += __shfl_down_sync(~0u, ss, o); }
        if (threadIdx.x == 0) {
            float mu  = s / (float)GELEMS;
            float var = ss / (float)GELEMS - mu * mu;
            g_mu[bg] = mu;
            g_rs[bg] = rsqrtf(var + 1e-6f);
        }
    }
}

// ---------------- normalize + transpose to [tok, c] --------------------------
__global__ void gn_apply(const float* __restrict__ x,
                         const float* __restrict__ gamma,
                         const float* __restrict__ beta) {
    __shared__ float tile[32][33];
    int b  = blockIdx.z;
    int c0 = blockIdx.y * 32;
    int s0 = blockIdx.x * 32;
    int tx = threadIdx.x, ty = threadIdx.y;
    for (int i = ty; i < 32; i += 8) {
        int c = c0 + i;
        int bg = b * NGRP + (c >> 3);
        float v = x[((size_t)(b * CCH + c)) * BHW + s0 + tx];
        tile[i][tx] = (v - g_mu[bg]) * g_rs[bg] * gamma[c] + beta[c];
    }
    __syncthreads();
    for (int i = ty; i < 32; i += 8)
        g_t[((size_t)(b * BHW + s0 + i)) * CCH + c0 + tx] = tile[tx][i];
}

// ---------------- pack qkv weights -------------------------------------------
__global__ void pack_w(const float* __restrict__ wq, const float* __restrict__ wk,
                       const float* __restrict__ wv, const float* __restrict__ bq,
                       const float* __restrict__ bk, const float* __restrict__ bv) {
    int r = blockIdx.x, tid = threadIdx.x;
    const float* w = (r < 256) ? wq : (r < 512) ? wk : wv;
    const float* bb = (r < 256) ? bq : (r < 512) ? bk : bv;
    int rr = r & 255;
    g_wqkv[r * 256 + tid] = w[rr * 256 + tid];
    if (tid == 0) g_bqkv[r] = bb[rr];
}

// ---------------- mma helper -------------------------------------------------
__device__ __forceinline__ void mma_tf32(float* c, const unsigned* a, const unsigned* b) {
    asm volatile("mma.sync.aligned.m16n8k8.row.col.f32.tf32.tf32.f32 "
                 "{%0,%1,%2,%3}, {%4,%5,%6,%7}, {%8,%9}, {%0,%1,%2,%3};"
                 : "+f"(c[0]), "+f"(c[1]), "+f"(c[2]), "+f"(c[3])
                 : "r"(a[0]), "r"(a[1]), "r"(a[2]), "r"(a[3]), "r"(b[0]), "r"(b[1]));
}
__device__ __forceinline__ unsigned fu(float f) { return __float_as_uint(f); }

// ---------------- cp.async helpers -------------------------------------------
__device__ __forceinline__ void cp16(float* smem, const float* g) {
    unsigned s = (unsigned)__cvta_generic_to_shared(smem);
    asm volatile("cp.async.cg.shared.global [%0], [%1], 16;" :: "r"(s), "l"(g));
}
#define CP_COMMIT asm volatile("cp.async.commit_group;")
#define CP_WAIT0  asm volatile("cp.async.wait_group 0;")

// ---------------- GEMM: C[M,N] = A[M,K] @ W[N,K]^T + bias --------------------
__global__ __launch_bounds__(256)
void gemm_tf32(const float* __restrict__ A, const float* __restrict__ Bm,
               float* __restrict__ Cp, int N, int K, const float* __restrict__ bias) {
    const int m0 = blockIdx.y * 128;
    const int n0 = blockIdx.x * 128;
    const int tid  = threadIdx.x;
    const int lane = tid & 31;
    const int warp = tid >> 5;
    const int wm = warp >> 1, wn = warp & 1;
    const int g  = lane >> 2, t4 = lane & 3;

    __shared__ float As[128 * 36];
    __shared__ float Bs[128 * 36];

    float acc[2][8][4];
    #pragma unroll
    for (int mi = 0; mi < 2; mi++)
        #pragma unroll
        for (int ni = 0; ni < 8; ni++)
            #pragma unroll
            for (int e = 0; e < 4; e++) acc[mi][ni][e] = 0.f;

    for (int kc = 0; kc < K; kc += 32) {
        #pragma unroll
        for (int it = 0; it < 4; it++) {
            int idx = tid + it * 256;
            int row = idx >> 3, seg = idx & 7;
            *(float4*)(As + row * 36 + seg * 4) =
                *(const float4*)(A + (size_t)(m0 + row) * K + kc + seg * 4);
            *(float4*)(Bs + row * 36 + seg * 4) =
                *(const float4*)(Bm + (size_t)(n0 + row) * K + kc + seg * 4);
        }
        __syncthreads();

        #pragma unroll
        for (int ks = 0; ks < 4; ks++) {
            const int k0 = ks * 8;
            unsigned af[2][4];
            #pragma unroll
            for (int mi = 0; mi < 2; mi++) {
                int r = wm * 32 + mi * 16 + g;
                af[mi][0] = fu(As[r * 36 + k0 + t4]);
                af[mi][1] = fu(As[(r + 8) * 36 + k0 + t4]);
                af[mi][2] = fu(As[r * 36 + k0 + t4 + 4]);
                af[mi][3] = fu(As[(r + 8) * 36 + k0 + t4 + 4]);
            }
            unsigned bf[8][2];
            #pragma unroll
            for (int ni = 0; ni < 8; ni++) {
                int cc = wn * 64 + ni * 8 + g;
                bf[ni][0] = fu(Bs[cc * 36 + k0 + t4]);
                bf[ni][1] = fu(Bs[cc * 36 + k0 + t4 + 4]);
            }
            #pragma unroll
            for (int mi = 0; mi < 2; mi++)
                #pragma unroll
                for (int ni = 0; ni < 8; ni++)
                    mma_tf32(acc[mi][ni], af[mi], bf[ni]);
        }
        __syncthreads();
    }

    #pragma unroll
    for (int mi = 0; mi < 2; mi++) {
        int rbase = m0 + wm * 32 + mi * 16 + g;
        #pragma unroll
        for (int ni = 0; ni < 8; ni++) {
            int cc = n0 + wn * 64 + ni * 8 + t4 * 2;
            #pragma unroll
            for (int half = 0; half < 2; half++) {
                int rr = rbase + half * 8;
                float2 w;
                w.x = acc[mi][ni][half * 2 + 0] + bias[cc];
                w.y = acc[mi][ni][half * 2 + 1] + bias[cc + 1];
                *(float2*)(Cp + (size_t)rr * N + cc) = w;
            }
        }
    }
}

// ---------------- u = sigmoid(t @ wu^T + bu) ---------------------------------
__global__ void u_kernel(const float* __restrict__ wu, const float* __restrict__ bu,
                         float* __restrict__ dout_u) {
    int i = blockIdx.x * 8 + (threadIdx.x >> 5);
    int lane = threadIdx.x & 31;
    const float* t = g_t + (size_t)i * CCH;
    float s = 0.f;
    #pragma unroll
    for (int j = 0; j < 8; j++) s += t[lane + j * 32] * wu[lane + j * 32];
    #pragma unroll
    for (int o = 16; o; o >>= 1) s += __shfl_down_sync(~0u, s, o);
    if (lane == 0) {
        float uu = 1.f / (1.f + expf(-(s + bu[0])));
        g_u[i] = uu;
        dout_u[i] = uu;
    }
}

// ---------------- fused flash attention --------------------------------------
// BM=64 queries/CTA, BN=64 keys/iter, d=256. 8 warps: (wm 0..3)x(wn 0..1).
#define QSTR 260
#define KSTR 260
#define VSTR 264
#define SSTR 68
#define SQ_OFF  0
#define SK_OFF  16640
#define SV_OFF  33280
#define SS_OFF  50176
#define SU_OFF  54528
#define SM_OFF  54592
#define SL_OFF  54656
#define SAL_OFF 54720
#define FLASH_SMEM (54784 * 4)

__global__ __launch_bounds__(256, 1)
void flash_attn(const float* __restrict__ qkv, const float* __restrict__ u,
                float* __restrict__ o) {
    extern __shared__ float sm[];
    float* sQ  = sm + SQ_OFF;
    float* sK  = sm + SK_OFF;
    float* sV  = sm + SV_OFF;
    float* sS  = sm + SS_OFF;
    float* sU  = sm + SU_OFF;
    float* sMx = sm + SM_OFF;
    float* sL  = sm + SL_OFF;
    float* sAl = sm + SAL_OFF;

    int b = blockIdx.y, q0 = blockIdx.x * 64;
    int tid = threadIdx.x, lane = tid & 31, warp = tid >> 5;
    int wm = warp >> 1, wn = warp & 1, g = lane >> 2, t4 = lane & 3;
    size_t tokb = (size_t)b * BHW;
    const float* Qg = qkv + (tokb + q0) * 768;
    const float* Kg = qkv + tokb * 768 + 256;
    const float* Vg = qkv + tokb * 768 + 512;
    const float* Ug = u + tokb;

    // stage Q, K[0], U[0]
    for (int i = tid; i < 4096; i += 256) {
        int r = i >> 6, s = i & 63;
        cp16(sQ + r * QSTR + s * 4, Qg + (size_t)r * 768 + s * 4);
    }
    for (int i = tid; i < 4096; i += 256) {
        int r = i >> 6, s = i & 63;
        cp16(sK + r * KSTR + s * 4, Kg + (size_t)r * 768 + s * 4);
    }
    if (tid < 16) cp16(sU + tid * 4, Ug + tid * 4);
    CP_COMMIT;

    if (tid < 64) { sMx[tid] = -1e30f; sL[tid] = 0.f; }
    float accO[16][4];
    #pragma unroll
    for (int ni = 0; ni < 16; ni++)
        #pragma unroll
        for (int e = 0; e < 4; e++) accO[ni][e] = 0.f;

    CP_WAIT0; __syncthreads();

    const int ar = (wm * 16 + g) * QSTR;
    const int sr = (wm * 16 + g) * SSTR;

    for (int it = 0; it < 64; ++it) {
        // prefetch V[it] (overlaps with QK compute)
        {
            const float* vs = Vg + (size_t)it * 64 * 768;
            for (int i = tid; i < 4096; i += 256) {
                int r = i >> 6, s = i & 63;
                cp16(sV + r * VSTR + s * 4, vs + (size_t)r * 768 + s * 4);
            }
            CP_COMMIT;
        }

        // S = Q @ K^T (per warp: 16 rows x 32 key-cols)
        float sacc[4][4];
        #pragma unroll
        for (int ni = 0; ni < 4; ni++)
            #pragma unroll
            for (int e = 0; e < 4; e++) sacc[ni][e] = 0.f;
        #pragma unroll
        for (int ks = 0; ks < 32; ks++) {
            int k0 = ks * 8;
            unsigned av[4];
            av[0] = fu(sQ[ar + k0 + t4]);
            av[1] = fu(sQ[ar + 8 * QSTR + k0 + t4]);
            av[2] = fu(sQ[ar + k0 + t4 + 4]);
            av[3] = fu(sQ[ar + 8 * QSTR + k0 + t4 + 4]);
            #pragma unroll
            for (int ni = 0; ni < 4; ni++) {
                int kc = (wn * 32 + ni * 8 + g) * KSTR;
                unsigned bv2[2] = { fu(sK[kc + k0 + t4]), fu(sK[kc + k0 + t4 + 4]) };
                mma_tf32(sacc[ni], av, bv2);
            }
        }

        CP_WAIT0;  // V[it] landed (this thread's copies; barrier below covers all)

        // scale by 1/16 * u[key], write S tile to smem
        #pragma unroll
        for (int ni = 0; ni < 4; ni++) {
            int c = wn * 32 + ni * 8 + t4 * 2;
            float u0 = sU[c] * 0.0625f, u1 = sU[c + 1] * 0.0625f;
            *(float2*)&sS[sr + c]            = make_float2(sacc[ni][0] * u0, sacc[ni][1] * u1);
            *(float2*)&sS[sr + 8 * SSTR + c] = make_float2(sacc[ni][2] * u0, sacc[ni][3] * u1);
        }
        __syncthreads();

        // online softmax: 4 threads per row, 16 cols each
        {
            int row = tid >> 2, sub = tid & 3;
            float* p = sS + row * SSTR + sub * 16;
            float4 v[4];
            #pragma unroll
            for (int j = 0; j < 4; j++) v[j] = *(float4*)(p + j * 4);
            float mt = -1e30f;
            #pragma unroll
            for (int j = 0; j < 4; j++)
                mt = fmaxf(mt, fmaxf(fmaxf(v[j].x, v[j].y), fmaxf(v[j].z, v[j].w)));
            mt = fmaxf(mt, __shfl_xor_sync(~0u, mt, 1));
            mt = fmaxf(mt, __shfl_xor_sync(~0u, mt, 2));
            float mo = sMx[row];
            float mn = fmaxf(mo, mt);
            float ls = 0.f;
            #pragma unroll
            for (int j = 0; j < 4; j++) {
                v[j].x = __expf(v[j].x - mn); v[j].y = __expf(v[j].y - mn);
                v[j].z = __expf(v[j].z - mn); v[j].w = __expf(v[j].w - mn);
                ls += v[j].x + v[j].y + v[j].z + v[j].w;
                *(float4*)(p + j * 4) = v[j];
            }
            ls += __shfl_xor_sync(~0u, ls, 1);
            ls += __shfl_xor_sync(~0u, ls, 2);
            if (sub == 0) {
                float al = __expf(mo - mn);
                sAl[row] = al;
                sL[row]  = sL[row] * al + ls;
                sMx[row] = mn;
            }
        }
        __syncthreads();

        // stage K[it+1] + U[it+1] (overlaps with PV compute)
        if (it + 1 < 64) {
            const float* ksrc = Kg + (size_t)(it + 1) * 64 * 768;
            for (int i = tid; i < 4096; i += 256) {
                int r = i >> 6, s = i & 63;
                cp16(sK + r * KSTR + s * 4, ksrc + (size_t)r * 768 + s * 4);
            }
            if (tid < 16) cp16(sU + tid * 4, Ug + (it + 1) * 64 + tid * 4);
            CP_COMMIT;
        }

        // rescale O, then O += P @ V (per warp: 16 rows x 128 d-cols)
        {
            int r0 = wm * 16 + g;
            float a0 = sAl[r0], a1 = sAl[r0 + 8];
            #pragma unroll
            for (int ni = 0; ni < 16; ni++) {
                accO[ni][0] *= a0; accO[ni][1] *= a0;
                accO[ni][2] *= a1; accO[ni][3] *= a1;
            }
            #pragma unroll
            for (int ks = 0; ks < 8; ks++) {
                int k0 = ks * 8;
                unsigned av[4];
                av[0] = fu(sS[sr + k0 + t4]);
                av[1] = fu(sS[sr + 8 * SSTR + k0 + t4]);
                av[2] = fu(sS[sr + k0 + t4 + 4]);
                av[3] = fu(sS[sr + 8 * SSTR + k0 + t4 + 4]);
                #pragma unroll
                for (int ni = 0; ni < 16; ni++) {
                    int c = wn * 128 + ni * 8 + g;
                    unsigned bv2[2] = { fu(sV[(k0 + t4) * VSTR + c]),
                                        fu(sV[(k0 + t4 + 4) * VSTR + c]) };
                    mma_tf32(accO[ni], av, bv2);
                }
            }
        }
        if (it + 1 < 64) { CP_WAIT0; }
        __syncthreads();
    }

    // epilogue: O /= l, write [tok, 256]
    int r0 = wm * 16 + g;
    float i0 = 1.f / sL[r0], i1 = 1.f / sL[r0 + 8];
    float* o0 = o + (tokb + q0 + r0) * 256;
    float* o1 = o + (tokb + q0 + r0 + 8) * 256;
    #pragma unroll
    for (int ni = 0; ni < 16; ni++) {
        int c = wn * 128 + ni * 8 + t4 * 2;
        *(float2*)&o0[c] = make_float2(accO[ni][0] * i0, accO[ni][1] * i0);
        *(float2*)&o1[c] = make_float2(accO[ni][2] * i1, accO[ni][3] * i1);
    }
}

// ---------------- final: out = x + y^T (per batch), transpose ----------------
__global__ void final_out(const float* __restrict__ x, float* __restrict__ out) {
    __shared__ float tile[32][33];
    int b  = blockIdx.z;
    int c0 = blockIdx.y * 32;
    int s0 = blockIdx.x * 32;
    int tx = threadIdx.x, ty = threadIdx.y;
    for (int i = ty; i < 32; i += 8)
        tile[i][tx] = g_y[((size_t)(b * BHW + s0 + i)) * CCH + c0 + tx];
    __syncthreads();
    for (int i = ty; i < 32; i += 8) {
        size_t idx = ((size_t)(b * CCH + c0 + i)) * BHW + s0 + tx;
        out[idx] = x[idx] + tile[tx][i];
    }
}

// ---------------- launch -----------------------------------------------------
extern "C" void kernel_launch(void* const* d_in, const int* in_sizes, int n_in,
                              void* d_out, int out_size) {
    (void)in_sizes; (void)n_in; (void)out_size;
    const float* x     = (const float*)d_in[0];
    const float* gamma = (const float*)d_in[1];
    const float* beta  = (const float*)d_in[2];
    const float* wq    = (const float*)d_in[3];
    const float* bq    = (const float*)d_in[4];
    const float* wk    = (const float*)d_in[5];
    const float* bk    = (const float*)d_in[6];
    const float* wv    = (const float*)d_in[7];
    const float* bv    = (const float*)d_in[8];
    const float* wu    = (const float*)d_in[9];
    const float* bu    = (const float*)d_in[10];
    const float* wp    = (const float*)d_in[11];
    const float* bp    = (const float*)d_in[12];
    float* out = (float*)d_out;

    float *pt, *pqkv, *po, *py, *pu, *pw, *pb;
    cudaGetSymbolAddress((void**)&pt,   g_t);
    cudaGetSymbolAddress((void**)&pqkv, g_qkv);
    cudaGetSymbolAddress((void**)&po,   g_o);
    cudaGetSymbolAddress((void**)&py,   g_y);
    cudaGetSymbolAddress((void**)&pu,   g_u);
    cudaGetSymbolAddress((void**)&pw,   g_wqkv);
    cudaGetSymbolAddress((void**)&pb,   g_bqkv);

    cudaFuncSetAttribute(flash_attn, cudaFuncAttributeMaxDynamicSharedMemorySize, FLASH_SMEM);

    // 1) GroupNorm
    gn_stats<<<NBAT * NGRP, 256>>>(x);
    gn_apply<<<dim3(BHW / 32, CCH / 32, NBAT), dim3(32, 8)>>>(x, gamma, beta);

    // 2) pack weights + fused QKV: [16384,768] = t @ Wqkv^T + b
    pack_w<<<768, 256>>>(wq, wk, wv, bq, bk, bv);
    gemm_tf32<<<dim3(6, 128), 256>>>(pt, pw, pqkv, 768, 256, pb);

    // 3) gate (also writes u_map part of output)
    u_kernel<<<NTOK / 8, 256>>>(wu, bu, out + OUT_MAIN);

    // 4) fused flash attention (scores + u-scale + softmax + PV)
    flash_attn<<<dim3(BHW / 64, NBAT), 256, FLASH_SMEM>>>(pqkv, pu, po);

    // 5) projection
    gemm_tf32<<<dim3(2, 128), 256>>>(po, wp, py, 256, 256, bp);

    // 6) residual + transpose back to [B,C,H,W]
    final_out<<<dim3(BHW / 32, CCH / 32, NBAT), dim3(32, 8)>>>(x, out);
}

// round 8
// speedup vs baseline: 1.2380x; 1.2380x over previous
#include <cuda_runtime.h>
#include <math.h>
#include <stdint.h>

#define BHW   4096
#define CCH   256
#define NBAT  4
#define NTOK  16384
#define NGRP  32
#define GELEMS (8*BHW)
#define OUT_MAIN ((size_t)NBAT*CCH*BHW)

#define BM 64
#define BN 32
#define FITERS 128
// smem float offsets for flash2
#define KOFF(i) ((i) * 8320)             /* [32][260] x2 */
#define VOFF(j) (16640 + (j) * 8448)     /* [32][264] x3 */
#define QSTG    16640                    /* 64x256 staging, overlaps V (read before V loads) */
#define POFF(p) (41984 + (p) * 2304)     /* [64][36] x2 */
#define SLOFF   46592
#define FSMEM   (46656 * 4)

__device__ float g_t[(size_t)NTOK*CCH];
__device__ float g_qkv[(size_t)NTOK*768];
__device__ float g_o[(size_t)NTOK*CCH];
__device__ float g_y[(size_t)NTOK*CCH];
__device__ float g_u[NTOK];
__device__ float g_wqkv[768*256];
__device__ float g_bqkv[768];
__device__ float g_mu[NBAT*NGRP];
__device__ float g_rs[NBAT*NGRP];

__device__ __forceinline__ unsigned fu(float f) { return __float_as_uint(f); }
__device__ __forceinline__ void mma_tf32(float* c, const unsigned* a, const unsigned* b) {
    asm volatile("mma.sync.aligned.m16n8k8.row.col.f32.tf32.tf32.f32 "
                 "{%0,%1,%2,%3}, {%4,%5,%6,%7}, {%8,%9}, {%0,%1,%2,%3};"
                 : "+f"(c[0]), "+f"(c[1]), "+f"(c[2]), "+f"(c[3])
                 : "r"(a[0]), "r"(a[1]), "r"(a[2]), "r"(a[3]), "r"(b[0]), "r"(b[1]));
}
__device__ __forceinline__ uint32_t smem_u32(const void* p) {
    uint32_t a;
    asm("{ .reg .u64 t; cvta.to.shared.u64 t, %1; cvt.u32.u64 %0, t; }" : "=r"(a) : "l"(p));
    return a;
}
__device__ __forceinline__ void cp16(uint32_t saddr, const float* g) {
    asm volatile("cp.async.cg.shared.global [%0], [%1], 16;" :: "r"(saddr), "l"(g));
}
#define CP_COMMIT asm volatile("cp.async.commit_group;" ::: "memory")
#define CP_WAIT0  asm volatile("cp.async.wait_group 0;" ::: "memory")

// ---------------- GroupNorm --------------------------------------------------
__global__ void gn_stats(const float* __restrict__ x) {
    int bg = blockIdx.x;
    const float4* p = (const float4*)(x + (size_t)bg * GELEMS);
    float s = 0.f, ss = 0.f;
    for (int i = threadIdx.x; i < GELEMS/4; i += blockDim.x) {
        float4 v = p[i];
        s += v.x + v.y + v.z + v.w;
        ss += v.x*v.x + v.y*v.y + v.z*v.z + v.w*v.w;
    }
    __shared__ float rs[8], rss[8];
    #pragma unroll
    for (int o = 16; o; o >>= 1) { s += __shfl_down_sync(~0u, s, o); ss += __shfl_down_sync(~0u, ss, o); }
    if ((threadIdx.x & 31) == 0) { rs[threadIdx.x >> 5] = s; rss[threadIdx.x >> 5] = ss; }
    __syncthreads();
    if (threadIdx.x < 32) {
        s  = (threadIdx.x < 8) ? rs[threadIdx.x]  : 0.f;
        ss = (threadIdx.x < 8) ? rss[threadIdx.x] : 0.f;
        #pragma unroll
        for (int o = 4; o; o >>= 1) { s += __shfl_down_sync(~0u, s, o); ss += __shfl_down_sync(~0u, ss, o); }
        if (threadIdx.x == 0) {
            float mu = s / (float)GELEMS;
            float var = ss / (float)GELEMS - mu * mu;
            g_mu[bg] = mu; g_rs[bg] = rsqrtf(var + 1e-6f);
        }
    }
}

__global__ void gn_apply(const float* __restrict__ x, const float* __restrict__ gamma,
                         const float* __restrict__ beta) {
    __shared__ float tile[32][33];
    int b = blockIdx.z, c0 = blockIdx.y * 32, s0 = blockIdx.x * 32;
    int tx = threadIdx.x, ty = threadIdx.y;
    for (int i = ty; i < 32; i += 8) {
        int c = c0 + i, bg = b * NGRP + (c >> 3);
        float v = x[((size_t)(b * CCH + c)) * BHW + s0 + tx];
        tile[i][tx] = (v - g_mu[bg]) * g_rs[bg] * gamma[c] + beta[c];
    }
    __syncthreads();
    for (int i = ty; i < 32; i += 8)
        g_t[((size_t)(b * BHW + s0 + i)) * CCH + c0 + tx] = tile[tx][i];
}

__global__ void pack_w(const float* __restrict__ wq, const float* __restrict__ wk,
                       const float* __restrict__ wv, const float* __restrict__ bq,
                       const float* __restrict__ bk, const float* __restrict__ bv) {
    int r = blockIdx.x, tid = threadIdx.x;
    const float* w = (r < 256) ? wq : (r < 512) ? wk : wv;
    const float* bb = (r < 256) ? bq : (r < 512) ? bk : bv;
    int rr = r & 255;
    g_wqkv[r * 256 + tid] = w[rr * 256 + tid];
    if (tid == 0) g_bqkv[r] = bb[rr];
}

// ---------- GEMM C=A@W^T+bias (EPI1: cols [256,512) *= u[row]/16) -----------
template<int EPI>
__global__ __launch_bounds__(256, 2)
void gemm_tf32(const float* __restrict__ A, const float* __restrict__ Bm,
               float* __restrict__ Cp, int N, int K, const float* __restrict__ bias,
               const float* __restrict__ urow) {
    const int m0 = blockIdx.y * 128, n0 = blockIdx.x * 128;
    const int tid = threadIdx.x, lane = tid & 31, warp = tid >> 5;
    const int wm = warp >> 1, wn = warp & 1, g = lane >> 2, t4 = lane & 3;
    __shared__ float As[128 * 36];
    __shared__ float Bs[128 * 36];
    float acc[2][8][4];
    #pragma unroll
    for (int mi = 0; mi < 2; mi++)
        #pragma unroll
        for (int ni = 0; ni < 8; ni++)
            #pragma unroll
            for (int e = 0; e < 4; e++) acc[mi][ni][e] = 0.f;

    for (int kc = 0; kc < K; kc += 32) {
        #pragma unroll
        for (int it = 0; it < 4; it++) {
            int idx = tid + it * 256, row = idx >> 3, seg = idx & 7;
            *(float4*)(As + row * 36 + seg * 4) =
                *(const float4*)(A + (size_t)(m0 + row) * K + kc + seg * 4);
            *(float4*)(Bs + row * 36 + seg * 4) =
                *(const float4*)(Bm + (size_t)(n0 + row) * K + kc + seg * 4);
        }
        __syncthreads();
        #pragma unroll
        for (int ks = 0; ks < 4; ks++) {
            const int k0 = ks * 8;
            unsigned af[2][4];
            #pragma unroll
            for (int mi = 0; mi < 2; mi++) {
                int r = wm * 32 + mi * 16 + g;
                af[mi][0] = fu(As[r * 36 + k0 + t4]);
                af[mi][1] = fu(As[(r + 8) * 36 + k0 + t4]);
                af[mi][2] = fu(As[r * 36 + k0 + t4 + 4]);
                af[mi][3] = fu(As[(r + 8) * 36 + k0 + t4 + 4]);
            }
            #pragma unroll
            for (int ni = 0; ni < 8; ni++) {
                int cc = wn * 64 + ni * 8 + g;
                unsigned bf[2] = { fu(Bs[cc * 36 + k0 + t4]), fu(Bs[cc * 36 + k0 + t4 + 4]) };
                mma_tf32(acc[0][ni], af[0], bf);
                mma_tf32(acc[1][ni], af[1], bf);
            }
        }
        __syncthreads();
    }
    #pragma unroll
    for (int mi = 0; mi < 2; mi++) {
        int rbase = m0 + wm * 32 + mi * 16 + g;
        #pragma unroll
        for (int ni = 0; ni < 8; ni++) {
            int cc = n0 + wn * 64 + ni * 8 + t4 * 2;
            #pragma unroll
            for (int half = 0; half < 2; half++) {
                int rr = rbase + half * 8;
                float v0 = acc[mi][ni][half * 2 + 0] + bias[cc];
                float v1 = acc[mi][ni][half * 2 + 1] + bias[cc + 1];
                if (EPI == 1 && cc >= 256 && cc < 512) {
                    float us = urow[rr] * 0.0625f;
                    v0 *= us; v1 *= us;
                }
                *(float2*)(Cp + (size_t)rr * N + cc) = make_float2(v0, v1);
            }
        }
    }
}

// ---------------- u = sigmoid(t @ wu^T + bu) ---------------------------------
__global__ void u_kernel(const float* __restrict__ wu, const float* __restrict__ bu,
                         float* __restrict__ dout_u) {
    int i = blockIdx.x * 8 + (threadIdx.x >> 5);
    int lane = threadIdx.x & 31;
    const float* t = g_t + (size_t)i * CCH;
    float s = 0.f;
    #pragma unroll
    for (int j = 0; j < 8; j++) s += t[lane + j * 32] * wu[lane + j * 32];
    #pragma unroll
    for (int o = 16; o; o >>= 1) s += __shfl_down_sync(~0u, s, o);
    if (lane == 0) {
        float uu = 1.f / (1.f + expf(-(s + bu[0])));
        g_u[i] = uu; dout_u[i] = uu;
    }
}

// ---------------- warp-specialized flash -------------------------------------
__global__ __launch_bounds__(256, 1)
void flash2(const float* __restrict__ qkv, float* __restrict__ o) {
    extern __shared__ float dsm[];
    uint32_t sb = smem_u32(dsm);
    int b = blockIdx.y, q0 = blockIdx.x * BM;
    int tid = threadIdx.x, lane = tid & 31, warp = tid >> 5;
    int g = lane >> 2, t4 = lane & 3;
    size_t tokb = (size_t)b * BHW;
    const float* Qg = qkv + (tokb + q0) * 768;
    const float* Kg = qkv + tokb * 768 + 256;
    const float* Vg = qkv + tokb * 768 + 512;

    // stage Q (into V area), read fragments to regs, then release area
    for (int i = tid; i < 4096; i += 256) {
        int r = i >> 6, c4 = (i & 63) * 4;
        cp16(sb + (QSTG + r * 256 + c4) * 4, Qg + (size_t)r * 768 + c4);
    }
    CP_COMMIT; CP_WAIT0; __syncthreads();

    float rp[128];   // QK warps: Q frags. PV warps: O accumulator.
    if (warp < 4) {
        int r0 = warp * 16 + g;
        const float* q = dsm + QSTG;
        #pragma unroll
        for (int ks = 0; ks < 32; ks++) {
            rp[ks*4+0] = q[r0 * 256 + ks * 8 + t4];
            rp[ks*4+1] = q[(r0 + 8) * 256 + ks * 8 + t4];
            rp[ks*4+2] = q[r0 * 256 + ks * 8 + t4 + 4];
            rp[ks*4+3] = q[(r0 + 8) * 256 + ks * 8 + t4 + 4];
        }
    } else {
        #pragma unroll
        for (int j = 0; j < 128; j++) rp[j] = 0.f;
    }
    __syncthreads();

    for (int i = tid; i < 2048; i += 256) {
        int r = i >> 6, c4 = (i & 63) * 4;
        cp16(sb + (KOFF(0) + r * 260 + c4) * 4, Kg + (size_t)r * 768 + c4);
        cp16(sb + (VOFF(0) + r * 264 + c4) * 4, Vg + (size_t)r * 768 + c4);
    }
    CP_COMMIT;

    float laccA = 0.f, laccB = 0.f;
    for (int it = 0; it <= FITERS; ++it) {
        CP_WAIT0;
        __syncthreads();
        if (it + 1 < FITERS) {
            const float* kn = Kg + (size_t)(it + 1) * BN * 768;
            const float* vn = Vg + (size_t)(it + 1) * BN * 768;
            int kd = KOFF((it + 1) & 1), vd = VOFF((it + 1) % 3);
            for (int i = tid; i < 2048; i += 256) {
                int r = i >> 6, c4 = (i & 63) * 4;
                cp16(sb + (kd + r * 260 + c4) * 4, kn + (size_t)r * 768 + c4);
                cp16(sb + (vd + r * 264 + c4) * 4, vn + (size_t)r * 768 + c4);
            }
            CP_COMMIT;
        }
        if (warp < 4) {
            if (it < FITERS) {
                const float* kb = dsm + KOFF(it & 1);
                float sacc[4][4];
                #pragma unroll
                for (int ni = 0; ni < 4; ni++)
                    #pragma unroll
                    for (int e = 0; e < 4; e++) sacc[ni][e] = 0.f;
                #pragma unroll
                for (int ks = 0; ks < 32; ks++) {
                    unsigned af[4] = { fu(rp[ks*4]), fu(rp[ks*4+1]), fu(rp[ks*4+2]), fu(rp[ks*4+3]) };
                    #pragma unroll
                    for (int ni = 0; ni < 4; ni++) {
                        unsigned bf[2] = { fu(kb[(ni*8+g)*260 + ks*8 + t4]),
                                           fu(kb[(ni*8+g)*260 + ks*8 + t4 + 4]) };
                        mma_tf32(sacc[ni], af, bf);
                    }
                }
                float* P = dsm + POFF(it & 1);
                int r0 = warp * 16 + g;
                #pragma unroll
                for (int ni = 0; ni < 4; ni++) {
                    float e0 = __expf(sacc[ni][0]), e1 = __expf(sacc[ni][1]);
                    float e2 = __expf(sacc[ni][2]), e3 = __expf(sacc[ni][3]);
                    laccA += e0 + e1; laccB += e2 + e3;
                    *(float2*)&P[r0 * 36 + ni*8 + t4*2]       = make_float2(e0, e1);
                    *(float2*)&P[(r0 + 8) * 36 + ni*8 + t4*2] = make_float2(e2, e3);
                }
                if (it == FITERS - 1) {
                    laccA += __shfl_xor_sync(~0u, laccA, 1);
                    laccA += __shfl_xor_sync(~0u, laccA, 2);
                    laccB += __shfl_xor_sync(~0u, laccB, 1);
                    laccB += __shfl_xor_sync(~0u, laccB, 2);
                    if (t4 == 0) { dsm[SLOFF + r0] = laccA; dsm[SLOFF + r0 + 8] = laccB; }
                }
            }
        } else if (it >= 1) {
            int pit = it - 1;
            const float* P = dsm + POFF(pit & 1);
            const float* V = dsm + VOFF(pit % 3);
            int w = warp - 4, wm = w & 1, wn = w >> 1;
            #pragma unroll
            for (int ks = 0; ks < 4; ks++) {
                unsigned af[2][4];
                #pragma unroll
                for (int mi = 0; mi < 2; mi++) {
                    int r = wm * 32 + mi * 16 + g;
                    af[mi][0] = fu(P[r * 36 + ks*8 + t4]);
                    af[mi][1] = fu(P[(r + 8) * 36 + ks*8 + t4]);
                    af[mi][2] = fu(P[r * 36 + ks*8 + t4 + 4]);
                    af[mi][3] = fu(P[(r + 8) * 36 + ks*8 + t4 + 4]);
                }
                #pragma unroll
                for (int ni = 0; ni < 16; ni++) {
                    unsigned bf[2] = { fu(V[(ks*8 + t4) * 264 + wn*128 + ni*8 + g]),
                                       fu(V[(ks*8 + t4 + 4) * 264 + wn*128 + ni*8 + g]) };
                    mma_tf32(&rp[ni*4],      af[0], bf);
                    mma_tf32(&rp[64 + ni*4], af[1], bf);
                }
            }
        }
    }

    if (warp >= 4) {   // epilogue: normalize, store [tok,256]
        int w = warp - 4, wm = w & 1, wn = w >> 1;
        #pragma unroll
        for (int mi = 0; mi < 2; mi++) {
            int r = wm * 32 + mi * 16 + g;
            float i0 = 1.f / dsm[SLOFF + r];
            float i1 = 1.f / dsm[SLOFF + r + 8];
            float* o0 = o + (tokb + q0 + r) * 256;
            float* o1 = o + (tokb + q0 + r + 8) * 256;
            #pragma unroll
            for (int ni = 0; ni < 16; ni++) {
                int cc = wn * 128 + ni * 8 + t4 * 2;
                float* a = &rp[mi * 64 + ni * 4];
                *(float2*)&o0[cc] = make_float2(a[0] * i0, a[1] * i0);
                *(float2*)&o1[cc] = make_float2(a[2] * i1, a[3] * i1);
            }
        }
    }
}

// ---------------- final: out = x + y^T ---------------------------------------
__global__ void final_out(const float* __restrict__ x, float* __restrict__ out) {
    __shared__ float tile[32][33];
    int b = blockIdx.z, c0 = blockIdx.y * 32, s0 = blockIdx.x * 32;
    int tx = threadIdx.x, ty = threadIdx.y;
    for (int i = ty; i < 32; i += 8)
        tile[i][tx] = g_y[((size_t)(b * BHW + s0 + i)) * CCH + c0 + tx];
    __syncthreads();
    for (int i = ty; i < 32; i += 8) {
        size_t idx = ((size_t)(b * CCH + c0 + i)) * BHW + s0 + tx;
        out[idx] = x[idx] + tile[tx][i];
    }
}

// ---------------- launch -----------------------------------------------------
extern "C" void kernel_launch(void* const* d_in, const int* in_sizes, int n_in,
                              void* d_out, int out_size) {
    (void)in_sizes; (void)n_in; (void)out_size;
    const float* x     = (const float*)d_in[0];
    const float* gamma = (const float*)d_in[1];
    const float* beta  = (const float*)d_in[2];
    const float* wq = (const float*)d_in[3],  *bq = (const float*)d_in[4];
    const float* wk = (const float*)d_in[5],  *bk = (const float*)d_in[6];
    const float* wv = (const float*)d_in[7],  *bv = (const float*)d_in[8];
    const float* wu = (const float*)d_in[9],  *bu = (const float*)d_in[10];
    const float* wp = (const float*)d_in[11], *bp = (const float*)d_in[12];
    float* out = (float*)d_out;

    float *pt, *pqkv, *po, *py, *pu, *pw, *pb;
    cudaGetSymbolAddress((void**)&pt,   g_t);
    cudaGetSymbolAddress((void**)&pqkv, g_qkv);
    cudaGetSymbolAddress((void**)&po,   g_o);
    cudaGetSymbolAddress((void**)&py,   g_y);
    cudaGetSymbolAddress((void**)&pu,   g_u);
    cudaGetSymbolAddress((void**)&pw,   g_wqkv);
    cudaGetSymbolAddress((void**)&pb,   g_bqkv);

    cudaFuncSetAttribute(flash2, cudaFuncAttributeMaxDynamicSharedMemorySize, FSMEM);

    gn_stats<<<NBAT * NGRP, 256>>>(x);
    gn_apply<<<dim3(BHW / 32, CCH / 32, NBAT), dim3(32, 8)>>>(x, gamma, beta);
    u_kernel<<<NTOK / 8, 256>>>(wu, bu, out + OUT_MAIN);
    pack_w<<<768, 256>>>(wq, wk, wv, bq, bk, bv);
    gemm_tf32<1><<<dim3(6, 128), 256>>>(pt, pw, pqkv, 768, 256, pb, pu);
    flash2<<<dim3(BHW / BM, NBAT), 256, FSMEM>>>(pqkv, po);
    gemm_tf32<0><<<dim3(2, 128), 256>>>(po, wp, py, 256, 256, bp, nullptr);
    final_out<<<dim3(BHW / 32, CCH / 32, NBAT), dim3(32, 8)>>>(x, out);
}

// round 9
// speedup vs baseline: 1.4639x; 1.1824x over previous
#include <cuda_runtime.h>
#include <cuda_bf16.h>
#include <math.h>
#include <stdint.h>

#define BHW   4096
#define CCH   256
#define NBAT  4
#define NTOK  16384
#define NGRP  32
#define GELEMS (8*BHW)
#define OUT_MAIN ((size_t)NBAT*CCH*BHW)

#define BM 64
#define BN 32
#define FITERS 128
// flash smem word offsets
#define KW(i)  ((i)*8320)                 /* K fp32 [32][260] x2 */
#define VW(j)  (16640 + (j)*4224)         /* V bf16x2 [16][264] x3 */
#define SW(p)  (29312 + (p)*2304)         /* S fp32 [64][36] x2 */
#define SLW    33920
#define QSTGW  16640                      /* Q staging overlaps V/S (used first) */
#define FSMEM  (33984*4)

__device__ float g_t[(size_t)NTOK*CCH];
__device__ float g_qk[(size_t)NTOK*512];      // q | k*u/16
__device__ unsigned g_vp[(size_t)(NTOK/2)*256]; // v bf16, token-pair packed
__device__ float g_o[(size_t)NTOK*CCH];
__device__ float g_y[(size_t)NTOK*CCH];
__device__ float g_u[NTOK];
__device__ float g_mu[NBAT*NGRP];
__device__ float g_rs[NBAT*NGRP];

__device__ __forceinline__ unsigned fu(float f) { return __float_as_uint(f); }
__device__ __forceinline__ void mma_tf32(float* c, const unsigned* a, const unsigned* b) {
    asm volatile("mma.sync.aligned.m16n8k8.row.col.f32.tf32.tf32.f32 "
                 "{%0,%1,%2,%3}, {%4,%5,%6,%7}, {%8,%9}, {%0,%1,%2,%3};"
                 : "+f"(c[0]), "+f"(c[1]), "+f"(c[2]), "+f"(c[3])
                 : "r"(a[0]), "r"(a[1]), "r"(a[2]), "r"(a[3]), "r"(b[0]), "r"(b[1]));
}
__device__ __forceinline__ void mma_bf16(float* c, const unsigned* a, unsigned b0, unsigned b1) {
    asm volatile("mma.sync.aligned.m16n8k16.row.col.f32.bf16.bf16.f32 "
                 "{%0,%1,%2,%3}, {%4,%5,%6,%7}, {%8,%9}, {%0,%1,%2,%3};"
                 : "+f"(c[0]), "+f"(c[1]), "+f"(c[2]), "+f"(c[3])
                 : "r"(a[0]), "r"(a[1]), "r"(a[2]), "r"(a[3]), "r"(b0), "r"(b1));
}
__device__ __forceinline__ uint32_t smem_u32(const void* p) {
    uint32_t a;
    asm("{ .reg .u64 t; cvta.to.shared.u64 t, %1; cvt.u32.u64 %0, t; }" : "=r"(a) : "l"(p));
    return a;
}
__device__ __forceinline__ void cp16(uint32_t saddr, const void* g) {
    asm volatile("cp.async.cg.shared.global [%0], [%1], 16;" :: "r"(saddr), "l"(g));
}
#define CP_COMMIT asm volatile("cp.async.commit_group;" ::: "memory")
#define CP_WAIT0  asm volatile("cp.async.wait_group 0;" ::: "memory")
__device__ __forceinline__ unsigned pack_bf(float lo, float hi) {
    unsigned r;
    asm("cvt.rn.bf16x2.f32 %0, %1, %2;" : "=r"(r) : "f"(hi), "f"(lo));
    return r;
}

// ---------------- GroupNorm --------------------------------------------------
__global__ void gn_stats(const float* __restrict__ x) {
    int bg = blockIdx.x;
    const float4* p = (const float4*)(x + (size_t)bg * GELEMS);
    float s = 0.f, ss = 0.f;
    for (int i = threadIdx.x; i < GELEMS/4; i += blockDim.x) {
        float4 v = p[i];
        s += v.x + v.y + v.z + v.w;
        ss += v.x*v.x + v.y*v.y + v.z*v.z + v.w*v.w;
    }
    __shared__ float rs[8], rss[8];
    #pragma unroll
    for (int o = 16; o; o >>= 1) { s += __shfl_down_sync(~0u, s, o); ss += __shfl_down_sync(~0u, ss, o); }
    if ((threadIdx.x & 31) == 0) { rs[threadIdx.x >> 5] = s; rss[threadIdx.x >> 5] = ss; }
    __syncthreads();
    if (threadIdx.x < 32) {
        s  = (threadIdx.x < 8) ? rs[threadIdx.x]  : 0.f;
        ss = (threadIdx.x < 8) ? rss[threadIdx.x] : 0.f;
        #pragma unroll
        for (int o = 4; o; o >>= 1) { s += __shfl_down_sync(~0u, s, o); ss += __shfl_down_sync(~0u, ss, o); }
        if (threadIdx.x == 0) {
            float mu = s / (float)GELEMS;
            float var = ss / (float)GELEMS - mu * mu;
            g_mu[bg] = mu; g_rs[bg] = rsqrtf(var + 1e-6f);
        }
    }
}

__global__ void gn_apply(const float* __restrict__ x, const float* __restrict__ gamma,
                         const float* __restrict__ beta) {
    __shared__ float tile[32][33];
    int b = blockIdx.z, c0 = blockIdx.y * 32, s0 = blockIdx.x * 32;
    int tx = threadIdx.x, ty = threadIdx.y;
    for (int i = ty; i < 32; i += 8) {
        int c = c0 + i, bg = b * NGRP + (c >> 3);
        float v = x[((size_t)(b * CCH + c)) * BHW + s0 + tx];
        tile[i][tx] = (v - g_mu[bg]) * g_rs[bg] * gamma[c] + beta[c];
    }
    __syncthreads();
    for (int i = ty; i < 32; i += 8)
        g_t[((size_t)(b * BHW + s0 + i)) * CCH + c0 + tx] = tile[tx][i];
}

// ---------------- gemm core (K=256, A,W row-major stride 256) ----------------
__device__ __forceinline__ void gemm_core(const float* A, const float* W, int m0,
                                          float* As, float* Bs, float acc[2][8][4]) {
    const int tid = threadIdx.x, lane = tid & 31, warp = tid >> 5;
    const int wm = warp >> 1, wn = warp & 1, g = lane >> 2, t4 = lane & 3;
    #pragma unroll
    for (int mi = 0; mi < 2; mi++)
        #pragma unroll
        for (int ni = 0; ni < 8; ni++)
            #pragma unroll
            for (int e = 0; e < 4; e++) acc[mi][ni][e] = 0.f;
    for (int kc = 0; kc < 256; kc += 32) {
        #pragma unroll
        for (int it = 0; it < 4; it++) {
            int idx = tid + it * 256, row = idx >> 3, seg = idx & 7;
            *(float4*)(As + row * 36 + seg * 4) =
                *(const float4*)(A + (size_t)(m0 + row) * 256 + kc + seg * 4);
            *(float4*)(Bs + row * 36 + seg * 4) =
                *(const float4*)(W + (size_t)row * 256 + kc + seg * 4);
        }
        __syncthreads();
        #pragma unroll
        for (int ks = 0; ks < 4; ks++) {
            const int k0 = ks * 8;
            unsigned af[2][4];
            #pragma unroll
            for (int mi = 0; mi < 2; mi++) {
                int r = wm * 32 + mi * 16 + g;
                af[mi][0] = fu(As[r * 36 + k0 + t4]);
                af[mi][1] = fu(As[(r + 8) * 36 + k0 + t4]);
                af[mi][2] = fu(As[r * 36 + k0 + t4 + 4]);
                af[mi][3] = fu(As[(r + 8) * 36 + k0 + t4 + 4]);
            }
            #pragma unroll
            for (int ni = 0; ni < 8; ni++) {
                int cc = wn * 64 + ni * 8 + g;
                unsigned bf[2] = { fu(Bs[cc * 36 + k0 + t4]), fu(Bs[cc * 36 + k0 + t4 + 4]) };
                mma_tf32(acc[0][ni], af[0], bf);
                mma_tf32(acc[1][ni], af[1], bf);
            }
        }
        __syncthreads();
    }
}

// qkv: writes q,k (fp32, k scaled by u/16) to qkout[tok][512], v bf16-packed to vp
__global__ __launch_bounds__(256, 2)
void gemm_qkv(const float* __restrict__ A,
              const float* __restrict__ wq, const float* __restrict__ wk, const float* __restrict__ wv,
              const float* __restrict__ bq, const float* __restrict__ bk, const float* __restrict__ bv,
              float* __restrict__ qkout, unsigned* __restrict__ vp, const float* __restrict__ urow) {
    const int n0 = blockIdx.x * 128, m0 = blockIdx.y * 128;
    const float* W  = (n0 < 256) ? wq : (n0 < 512) ? wk : wv;
    const float* Bi = (n0 < 256) ? bq : (n0 < 512) ? bk : bv;
    W += (size_t)(n0 & 255) * 256;
    __shared__ float As[128 * 36];
    __shared__ float Bs[128 * 36];
    float acc[2][8][4];
    gemm_core(A, W, m0, As, Bs, acc);
    const int lane = threadIdx.x & 31, warp = threadIdx.x >> 5;
    const int wm = warp >> 1, wn = warp & 1, g = lane >> 2, t4 = lane & 3;
    #pragma unroll
    for (int mi = 0; mi < 2; mi++) {
        int rbase = m0 + wm * 32 + mi * 16 + g;
        #pragma unroll
        for (int ni = 0; ni < 8; ni++) {
            int cl = wn * 64 + ni * 8 + t4 * 2, cg = n0 + cl;
            #pragma unroll
            for (int half = 0; half < 2; half++) {
                int rr = rbase + half * 8;
                float v0 = acc[mi][ni][half * 2 + 0] + Bi[(n0 & 255) + cl];
                float v1 = acc[mi][ni][half * 2 + 1] + Bi[(n0 & 255) + cl + 1];
                if (cg < 512) {
                    if (cg >= 256) { float us = urow[rr] * 0.0625f; v0 *= us; v1 *= us; }
                    *(float2*)(qkout + (size_t)rr * 512 + cg) = make_float2(v0, v1);
                } else {
                    int c2 = cg - 512, t2 = rr >> 1, par = rr & 1;
                    __nv_bfloat16* vb = (__nv_bfloat16*)vp;
                    vb[((size_t)t2 * 256 + c2) * 2 + par]     = __float2bfloat16(v0);
                    vb[((size_t)t2 * 256 + c2 + 1) * 2 + par] = __float2bfloat16(v1);
                }
            }
        }
    }
}

__global__ __launch_bounds__(256, 2)
void gemm_proj(const float* __restrict__ A, const float* __restrict__ W,
               const float* __restrict__ bias, float* __restrict__ Cp) {
    const int n0 = blockIdx.x * 128, m0 = blockIdx.y * 128;
    __shared__ float As[128 * 36];
    __shared__ float Bs[128 * 36];
    float acc[2][8][4];
    gemm_core(A, W + (size_t)n0 * 256, m0, As, Bs, acc);
    const int lane = threadIdx.x & 31, warp = threadIdx.x >> 5;
    const int wm = warp >> 1, wn = warp & 1, g = lane >> 2, t4 = lane & 3;
    #pragma unroll
    for (int mi = 0; mi < 2; mi++) {
        int rbase = m0 + wm * 32 + mi * 16 + g;
        #pragma unroll
        for (int ni = 0; ni < 8; ni++) {
            int cl = wn * 64 + ni * 8 + t4 * 2, cg = n0 + cl;
            #pragma unroll
            for (int half = 0; half < 2; half++) {
                int rr = rbase + half * 8;
                *(float2*)(Cp + (size_t)rr * 256 + cg) =
                    make_float2(acc[mi][ni][half * 2 + 0] + bias[cg],
                                acc[mi][ni][half * 2 + 1] + bias[cg + 1]);
            }
        }
    }
}

// ---------------- u = sigmoid(t @ wu^T + bu) ---------------------------------
__global__ void u_kernel(const float* __restrict__ wu, const float* __restrict__ bu,
                         float* __restrict__ dout_u) {
    int i = blockIdx.x * 8 + (threadIdx.x >> 5);
    int lane = threadIdx.x & 31;
    const float* t = g_t + (size_t)i * CCH;
    float s = 0.f;
    #pragma unroll
    for (int j = 0; j < 8; j++) s += t[lane + j * 32] * wu[lane + j * 32];
    #pragma unroll
    for (int o = 16; o; o >>= 1) s += __shfl_down_sync(~0u, s, o);
    if (lane == 0) {
        float uu = 1.f / (1.f + expf(-(s + bu[0])));
        g_u[i] = uu; dout_u[i] = uu;
    }
}

// ---------------- balanced warp-specialized flash ----------------------------
__global__ __launch_bounds__(256, 1)
void flash3(const float* __restrict__ qk, const unsigned* __restrict__ vp,
            float* __restrict__ o) {
    extern __shared__ float dsm[];
    unsigned* dsu = (unsigned*)dsm;
    uint32_t sb = smem_u32(dsm);
    int b = blockIdx.y, q0 = blockIdx.x * BM;
    int tid = threadIdx.x, lane = tid & 31, warp = tid >> 5;
    int g = lane >> 2, t4 = lane & 3;
    size_t tokb = (size_t)b * BHW;
    const float* Qg = qk + (tokb + q0) * 512;
    const float* Kg = qk + tokb * 512 + 256;
    const unsigned* Vg = vp + (size_t)b * 2048 * 256;

    for (int i = tid; i < 4096; i += 256) {
        int r = i >> 6, c4 = (i & 63) * 4;
        cp16(sb + (QSTGW + r * 256 + c4) * 4, Qg + (size_t)r * 512 + c4);
    }
    CP_COMMIT; CP_WAIT0; __syncthreads();

    float rp[128];   // QK warps: Q frags. PV warps: O accumulator.
    if (warp < 4) {
        int r0 = warp * 16 + g;
        const float* q = dsm + QSTGW;
        #pragma unroll
        for (int ks = 0; ks < 32; ks++) {
            rp[ks*4+0] = q[r0 * 256 + ks * 8 + t4];
            rp[ks*4+1] = q[(r0 + 8) * 256 + ks * 8 + t4];
            rp[ks*4+2] = q[r0 * 256 + ks * 8 + t4 + 4];
            rp[ks*4+3] = q[(r0 + 8) * 256 + ks * 8 + t4 + 4];
        }
    } else {
        #pragma unroll
        for (int j = 0; j < 128; j++) rp[j] = 0.f;
    }
    __syncthreads();

    for (int i = tid; i < 2048; i += 256) {
        int r = i >> 6, c4 = (i & 63) * 4;
        cp16(sb + (KW(0) + r * 260 + c4) * 4, Kg + (size_t)r * 512 + c4);
    }
    for (int i = tid; i < 1024; i += 256) {
        int r = i >> 6, c4 = (i & 63) * 4;
        cp16(sb + (VW(0) + r * 264 + c4) * 4, Vg + (size_t)r * 256 + c4);
    }
    CP_COMMIT;

    int w = warp - 4, wm = w & 1, wn = w >> 1;
    float lac[4] = {0.f, 0.f, 0.f, 0.f};

    for (int it = 0; it <= FITERS; ++it) {
        CP_WAIT0; __syncthreads();
        if (it + 1 < FITERS) {
            const float* kn = Kg + (size_t)(it + 1) * BN * 512;
            const unsigned* vn = Vg + (size_t)(it + 1) * 16 * 256;
            int kd = KW((it + 1) & 1), vd = VW((it + 1) % 3);
            for (int i = tid; i < 2048; i += 256) {
                int r = i >> 6, c4 = (i & 63) * 4;
                cp16(sb + (kd + r * 260 + c4) * 4, kn + (size_t)r * 512 + c4);
            }
            for (int i = tid; i < 1024; i += 256) {
                int r = i >> 6, c4 = (i & 63) * 4;
                cp16(sb + (vd + r * 264 + c4) * 4, vn + (size_t)r * 256 + c4);
            }
            CP_COMMIT;
        }
        if (warp < 4) {
            if (it < FITERS) {        // QK: raw S only
                const float* kb = dsm + KW(it & 1);
                float sacc[4][4];
                #pragma unroll
                for (int ni = 0; ni < 4; ni++)
                    #pragma unroll
                    for (int e = 0; e < 4; e++) sacc[ni][e] = 0.f;
                #pragma unroll
                for (int ks = 0; ks < 32; ks++) {
                    unsigned af[4] = { fu(rp[ks*4]), fu(rp[ks*4+1]), fu(rp[ks*4+2]), fu(rp[ks*4+3]) };
                    #pragma unroll
                    for (int ni = 0; ni < 4; ni++) {
                        unsigned bf[2] = { fu(kb[(ni*8+g)*260 + ks*8 + t4]),
                                           fu(kb[(ni*8+g)*260 + ks*8 + t4 + 4]) };
                        mma_tf32(sacc[ni], af, bf);
                    }
                }
                float* S = dsm + SW(it & 1);
                int r0 = warp * 16 + g;
                #pragma unroll
                for (int ni = 0; ni < 4; ni++) {
                    *(float2*)&S[r0 * 36 + ni*8 + t4*2]       = make_float2(sacc[ni][0], sacc[ni][1]);
                    *(float2*)&S[(r0 + 8) * 36 + ni*8 + t4*2] = make_float2(sacc[ni][2], sacc[ni][3]);
                }
            }
        } else if (it >= 1) {          // PV: exp + bf16 mma
            int pit = it - 1;
            const float* S = dsm + SW(pit & 1);
            const unsigned* V = dsu + VW(pit % 3);
            unsigned af[2][2][4];
            #pragma unroll
            for (int mi = 0; mi < 2; mi++) {
                int r0 = wm * 32 + mi * 16 + g;
                #pragma unroll
                for (int k16 = 0; k16 < 2; k16++) {
                    float2 v00 = *(const float2*)&S[r0 * 36 + k16*16 + t4*2];
                    float2 v10 = *(const float2*)&S[(r0+8) * 36 + k16*16 + t4*2];
                    float2 v01 = *(const float2*)&S[r0 * 36 + k16*16 + 8 + t4*2];
                    float2 v11 = *(const float2*)&S[(r0+8) * 36 + k16*16 + 8 + t4*2];
                    float e0x = __expf(v00.x), e0y = __expf(v00.y);
                    float e1x = __expf(v10.x), e1y = __expf(v10.y);
                    float e2x = __expf(v01.x), e2y = __expf(v01.y);
                    float e3x = __expf(v11.x), e3y = __expf(v11.y);
                    if (wn == 0) {
                        lac[mi*2+0] += e0x + e0y + e2x + e2y;
                        lac[mi*2+1] += e1x + e1y + e3x + e3y;
                    }
                    af[mi][k16][0] = pack_bf(e0x, e0y);
                    af[mi][k16][1] = pack_bf(e1x, e1y);
                    af[mi][k16][2] = pack_bf(e2x, e2y);
                    af[mi][k16][3] = pack_bf(e3x, e3y);
                }
            }
            #pragma unroll
            for (int k16 = 0; k16 < 2; k16++) {
                #pragma unroll
                for (int ni = 0; ni < 16; ni++) {
                    int c = wn * 128 + ni * 8 + g;
                    unsigned b0 = V[(k16*8 + t4) * 264 + c];
                    unsigned b1 = V[(k16*8 + 4 + t4) * 264 + c];
                    mma_bf16(&rp[ni*4],      af[0][k16], b0, b1);
                    mma_bf16(&rp[64 + ni*4], af[1][k16], b0, b1);
                }
            }
        }
    }

    if (warp >= 4 && wn == 0) {   // l reduce (rows wm*32 + mi*16 + {g,g+8})
        #pragma unroll
        for (int j = 0; j < 4; j++) {
            lac[j] += __shfl_xor_sync(~0u, lac[j], 1);
            lac[j] += __shfl_xor_sync(~0u, lac[j], 2);
        }
        if (t4 == 0) {
            dsm[SLW + wm*32 + g]      = lac[0];
            dsm[SLW + wm*32 + g + 8]  = lac[1];
            dsm[SLW + wm*32 + g + 16] = lac[2];
            dsm[SLW + wm*32 + g + 24] = lac[3];
        }
    }
    __syncthreads();
    if (warp >= 4) {
        #pragma unroll
        for (int mi = 0; mi < 2; mi++) {
            int r = wm * 32 + mi * 16 + g;
            float i0 = 1.f / dsm[SLW + r];
            float i1 = 1.f / dsm[SLW + r + 8];
            float* o0 = o + (tokb + q0 + r) * 256;
            float* o1 = o + (tokb + q0 + r + 8) * 256;
            #pragma unroll
            for (int ni = 0; ni < 16; ni++) {
                int cc = wn * 128 + ni * 8 + t4 * 2;
                float* a = &rp[mi * 64 + ni * 4];
                *(float2*)&o0[cc] = make_float2(a[0] * i0, a[1] * i0);
                *(float2*)&o1[cc] = make_float2(a[2] * i1, a[3] * i1);
            }
        }
    }
}

// ---------------- final: out = x + y^T ---------------------------------------
__global__ void final_out(const float* __restrict__ x, float* __restrict__ out) {
    __shared__ float tile[32][33];
    int b = blockIdx.z, c0 = blockIdx.y * 32, s0 = blockIdx.x * 32;
    int tx = threadIdx.x, ty = threadIdx.y;
    for (int i = ty; i < 32; i += 8)
        tile[i][tx] = g_y[((size_t)(b * BHW + s0 + i)) * CCH + c0 + tx];
    __syncthreads();
    for (int i = ty; i < 32; i += 8) {
        size_t idx = ((size_t)(b * CCH + c0 + i)) * BHW + s0 + tx;
        out[idx] = x[idx] + tile[tx][i];
    }
}

// ---------------- launch -----------------------------------------------------
extern "C" void kernel_launch(void* const* d_in, const int* in_sizes, int n_in,
                              void* d_out, int out_size) {
    (void)in_sizes; (void)n_in; (void)out_size;
    const float* x     = (const float*)d_in[0];
    const float* gamma = (const float*)d_in[1];
    const float* beta  = (const float*)d_in[2];
    const float* wq = (const float*)d_in[3],  *bq = (const float*)d_in[4];
    const float* wk = (const float*)d_in[5],  *bk = (const float*)d_in[6];
    const float* wv = (const float*)d_in[7],  *bv = (const float*)d_in[8];
    const float* wu = (const float*)d_in[9],  *bu = (const float*)d_in[10];
    const float* wp = (const float*)d_in[11], *bp = (const float*)d_in[12];
    float* out = (float*)d_out;

    float *pt, *pqk, *po, *py, *pu;
    unsigned* pvp;
    cudaGetSymbolAddress((void**)&pt,  g_t);
    cudaGetSymbolAddress((void**)&pqk, g_qk);
    cudaGetSymbolAddress((void**)&pvp, g_vp);
    cudaGetSymbolAddress((void**)&po,  g_o);
    cudaGetSymbolAddress((void**)&py,  g_y);
    cudaGetSymbolAddress((void**)&pu,  g_u);

    cudaFuncSetAttribute(flash3, cudaFuncAttributeMaxDynamicSharedMemorySize, FSMEM);

    gn_stats<<<NBAT * NGRP, 256>>>(x);
    gn_apply<<<dim3(BHW / 32, CCH / 32, NBAT), dim3(32, 8)>>>(x, gamma, beta);
    u_kernel<<<NTOK / 8, 256>>>(wu, bu, out + OUT_MAIN);
    gemm_qkv<<<dim3(6, 128), 256>>>(pt, wq, wk, wv, bq, bk, bv, pqk, pvp, pu);
    flash3<<<dim3(BHW / BM, NBAT), 256, FSMEM>>>(pqk, pvp, po);
    gemm_proj<<<dim3(2, 128), 256>>>(po, wp, bp, py);
    final_out<<<dim3(BHW / 32, CCH / 32, NBAT), dim3(32, 8)>>>(x, out);
}

// round 10
// speedup vs baseline: 1.8744x; 1.2804x over previous
#include <cuda_runtime.h>
#include <cuda_bf16.h>
#include <cuda_fp16.h>
#include <math.h>
#include <stdint.h>

#define BHW   4096
#define CCH   256
#define NBAT  4
#define NTOK  16384
#define NGRP  32
#define GELEMS (8*BHW)
#define OUT_MAIN ((size_t)NBAT*CCH*BHW)

#define BM 64
#define BN 32
#define FITERS 128
// flash smem WORD offsets
#define KW(i)  ((i)*4224)                 /* K fp16 [32][264h] x2 */
#define VW(j)  (8448 + (j)*4224)          /* V bf16x2 [16][264] x3 */
#define QSTGW  8448                       /* Q fp16 staging [64][264h], used before V/S */
#define SW(p)  (21120 + (p)*2304)         /* S fp32 [64][36] x2 */
#define SLW    25728
#define FSMEM  (25792*4)

__device__ float    g_t[(size_t)NTOK*CCH];
__device__ __half   g_qkh[(size_t)NTOK*512];      // q | k*u/16 (fp16)
__device__ unsigned g_vp[(size_t)(NTOK/2)*256];   // v bf16, token-pair packed
__device__ float    g_o[(size_t)NTOK*CCH];
__device__ float    g_y[(size_t)NTOK*CCH];
__device__ float    g_u[NTOK];
__device__ float    g_mu[NBAT*NGRP];
__device__ float    g_rs[NBAT*NGRP];

__device__ __forceinline__ unsigned fu(float f) { return __float_as_uint(f); }
__device__ __forceinline__ void mma_tf32(float* c, const unsigned* a, const unsigned* b) {
    asm volatile("mma.sync.aligned.m16n8k8.row.col.f32.tf32.tf32.f32 "
                 "{%0,%1,%2,%3}, {%4,%5,%6,%7}, {%8,%9}, {%0,%1,%2,%3};"
                 : "+f"(c[0]), "+f"(c[1]), "+f"(c[2]), "+f"(c[3])
                 : "r"(a[0]), "r"(a[1]), "r"(a[2]), "r"(a[3]), "r"(b[0]), "r"(b[1]));
}
__device__ __forceinline__ void mma_f16(float* c, const unsigned* a, unsigned b0, unsigned b1) {
    asm volatile("mma.sync.aligned.m16n8k16.row.col.f32.f16.f16.f32 "
                 "{%0,%1,%2,%3}, {%4,%5,%6,%7}, {%8,%9}, {%0,%1,%2,%3};"
                 : "+f"(c[0]), "+f"(c[1]), "+f"(c[2]), "+f"(c[3])
                 : "r"(a[0]), "r"(a[1]), "r"(a[2]), "r"(a[3]), "r"(b0), "r"(b1));
}
__device__ __forceinline__ void mma_bf16(float* c, const unsigned* a, unsigned b0, unsigned b1) {
    asm volatile("mma.sync.aligned.m16n8k16.row.col.f32.bf16.bf16.f32 "
                 "{%0,%1,%2,%3}, {%4,%5,%6,%7}, {%8,%9}, {%0,%1,%2,%3};"
                 : "+f"(c[0]), "+f"(c[1]), "+f"(c[2]), "+f"(c[3])
                 : "r"(a[0]), "r"(a[1]), "r"(a[2]), "r"(a[3]), "r"(b0), "r"(b1));
}
__device__ __forceinline__ uint32_t smem_u32(const void* p) {
    uint32_t a;
    asm("{ .reg .u64 t; cvta.to.shared.u64 t, %1; cvt.u32.u64 %0, t; }" : "=r"(a) : "l"(p));
    return a;
}
__device__ __forceinline__ void cp16(uint32_t saddr, const void* g) {
    asm volatile("cp.async.cg.shared.global [%0], [%1], 16;" :: "r"(saddr), "l"(g));
}
#define CP_COMMIT asm volatile("cp.async.commit_group;" ::: "memory")
#define CP_WAIT0  asm volatile("cp.async.wait_group 0;" ::: "memory")
__device__ __forceinline__ unsigned pack_bf(float lo, float hi) {
    unsigned r;
    asm("cvt.rn.bf16x2.f32 %0, %1, %2;" : "=r"(r) : "f"(hi), "f"(lo));
    return r;
}

// ---------------- GroupNorm --------------------------------------------------
__global__ void gn_stats(const float* __restrict__ x) {
    int bg = blockIdx.x;
    const float4* p = (const float4*)(x + (size_t)bg * GELEMS);
    float s = 0.f, ss = 0.f;
    for (int i = threadIdx.x; i < GELEMS/4; i += blockDim.x) {
        float4 v = p[i];
        s += v.x + v.y + v.z + v.w;
        ss += v.x*v.x + v.y*v.y + v.z*v.z + v.w*v.w;
    }
    __shared__ float rs[8], rss[8];
    #pragma unroll
    for (int o = 16; o; o >>= 1) { s += __shfl_down_sync(~0u, s, o); ss += __shfl_down_sync(~0u, ss, o); }
    if ((threadIdx.x & 31) == 0) { rs[threadIdx.x >> 5] = s; rss[threadIdx.x >> 5] = ss; }
    __syncthreads();
    if (threadIdx.x < 32) {
        s  = (threadIdx.x < 8) ? rs[threadIdx.x]  : 0.f;
        ss = (threadIdx.x < 8) ? rss[threadIdx.x] : 0.f;
        #pragma unroll
        for (int o = 4; o; o >>= 1) { s += __shfl_down_sync(~0u, s, o); ss += __shfl_down_sync(~0u, ss, o); }
        if (threadIdx.x == 0) {
            float mu = s / (float)GELEMS;
            float var = ss / (float)GELEMS - mu * mu;
            g_mu[bg] = mu; g_rs[bg] = rsqrtf(var + 1e-6f);
        }
    }
}

__global__ void gn_apply(const float* __restrict__ x, const float* __restrict__ gamma,
                         const float* __restrict__ beta) {
    __shared__ float tile[32][33];
    int b = blockIdx.z, c0 = blockIdx.y * 32, s0 = blockIdx.x * 32;
    int tx = threadIdx.x, ty = threadIdx.y;
    for (int i = ty; i < 32; i += 8) {
        int c = c0 + i, bg = b * NGRP + (c >> 3);
        float v = x[((size_t)(b * CCH + c)) * BHW + s0 + tx];
        tile[i][tx] = (v - g_mu[bg]) * g_rs[bg] * gamma[c] + beta[c];
    }
    __syncthreads();
    for (int i = ty; i < 32; i += 8)
        g_t[((size_t)(b * BHW + s0 + i)) * CCH + c0 + tx] = tile[tx][i];
}

// ---------------- gemm core (K=256) ------------------------------------------
__device__ __forceinline__ void gemm_core(const float* A, const float* W, int m0,
                                          float* As, float* Bs, float acc[2][8][4]) {
    const int tid = threadIdx.x, lane = tid & 31, warp = tid >> 5;
    const int wm = warp >> 1, wn = warp & 1, g = lane >> 2, t4 = lane & 3;
    #pragma unroll
    for (int mi = 0; mi < 2; mi++)
        #pragma unroll
        for (int ni = 0; ni < 8; ni++)
            #pragma unroll
            for (int e = 0; e < 4; e++) acc[mi][ni][e] = 0.f;
    for (int kc = 0; kc < 256; kc += 32) {
        #pragma unroll
        for (int it = 0; it < 4; it++) {
            int idx = tid + it * 256, row = idx >> 3, seg = idx & 7;
            *(float4*)(As + row * 36 + seg * 4) =
                *(const float4*)(A + (size_t)(m0 + row) * 256 + kc + seg * 4);
            *(float4*)(Bs + row * 36 + seg * 4) =
                *(const float4*)(W + (size_t)row * 256 + kc + seg * 4);
        }
        __syncthreads();
        #pragma unroll
        for (int ks = 0; ks < 4; ks++) {
            const int k0 = ks * 8;
            unsigned af[2][4];
            #pragma unroll
            for (int mi = 0; mi < 2; mi++) {
                int r = wm * 32 + mi * 16 + g;
                af[mi][0] = fu(As[r * 36 + k0 + t4]);
                af[mi][1] = fu(As[(r + 8) * 36 + k0 + t4]);
                af[mi][2] = fu(As[r * 36 + k0 + t4 + 4]);
                af[mi][3] = fu(As[(r + 8) * 36 + k0 + t4 + 4]);
            }
            #pragma unroll
            for (int ni = 0; ni < 8; ni++) {
                int cc = wn * 64 + ni * 8 + g;
                unsigned bf[2] = { fu(Bs[cc * 36 + k0 + t4]), fu(Bs[cc * 36 + k0 + t4 + 4]) };
                mma_tf32(acc[0][ni], af[0], bf);
                mma_tf32(acc[1][ni], af[1], bf);
            }
        }
        __syncthreads();
    }
}

// qkv: q,k -> fp16 (k scaled u/16); v -> bf16 token-pair packed
__global__ __launch_bounds__(256, 2)
void gemm_qkv(const float* __restrict__ A,
              const float* __restrict__ wq, const float* __restrict__ wk, const float* __restrict__ wv,
              const float* __restrict__ bq, const float* __restrict__ bk, const float* __restrict__ bv,
              __half* __restrict__ qkh, unsigned* __restrict__ vp, const float* __restrict__ urow) {
    const int n0 = blockIdx.x * 128, m0 = blockIdx.y * 128;
    const float* W  = (n0 < 256) ? wq : (n0 < 512) ? wk : wv;
    const float* Bi = (n0 < 256) ? bq : (n0 < 512) ? bk : bv;
    W += (size_t)(n0 & 255) * 256;
    __shared__ float As[128 * 36];
    __shared__ float Bs[128 * 36];
    float acc[2][8][4];
    gemm_core(A, W, m0, As, Bs, acc);
    const int lane = threadIdx.x & 31, warp = threadIdx.x >> 5;
    const int wm = warp >> 1, wn = warp & 1, g = lane >> 2, t4 = lane & 3;
    #pragma unroll
    for (int mi = 0; mi < 2; mi++) {
        int rbase = m0 + wm * 32 + mi * 16 + g;
        #pragma unroll
        for (int ni = 0; ni < 8; ni++) {
            int cl = wn * 64 + ni * 8 + t4 * 2, cg = n0 + cl;
            #pragma unroll
            for (int half = 0; half < 2; half++) {
                int rr = rbase + half * 8;
                float v0 = acc[mi][ni][half * 2 + 0] + Bi[(n0 & 255) + cl];
                float v1 = acc[mi][ni][half * 2 + 1] + Bi[(n0 & 255) + cl + 1];
                if (cg < 512) {
                    if (cg >= 256) { float us = urow[rr] * 0.0625f; v0 *= us; v1 *= us; }
                    *(__half2*)&qkh[(size_t)rr * 512 + cg] = __floats2half2_rn(v0, v1);
                } else {
                    int c2 = cg - 512, t2 = rr >> 1, par = rr & 1;
                    __nv_bfloat16* vb = (__nv_bfloat16*)vp;
                    vb[((size_t)t2 * 256 + c2) * 2 + par]     = __float2bfloat16(v0);
                    vb[((size_t)t2 * 256 + c2 + 1) * 2 + par] = __float2bfloat16(v1);
                }
            }
        }
    }
}

__global__ __launch_bounds__(256, 2)
void gemm_proj(const float* __restrict__ A, const float* __restrict__ W,
               const float* __restrict__ bias, float* __restrict__ Cp) {
    const int n0 = blockIdx.x * 128, m0 = blockIdx.y * 128;
    __shared__ float As[128 * 36];
    __shared__ float Bs[128 * 36];
    float acc[2][8][4];
    gemm_core(A, W + (size_t)n0 * 256, m0, As, Bs, acc);
    const int lane = threadIdx.x & 31, warp = threadIdx.x >> 5;
    const int wm = warp >> 1, wn = warp & 1, g = lane >> 2, t4 = lane & 3;
    #pragma unroll
    for (int mi = 0; mi < 2; mi++) {
        int rbase = m0 + wm * 32 + mi * 16 + g;
        #pragma unroll
        for (int ni = 0; ni < 8; ni++) {
            int cl = wn * 64 + ni * 8 + t4 * 2, cg = n0 + cl;
            #pragma unroll
            for (int half = 0; half < 2; half++) {
                int rr = rbase + half * 8;
                *(float2*)(Cp + (size_t)rr * 256 + cg) =
                    make_float2(acc[mi][ni][half * 2 + 0] + bias[cg],
                                acc[mi][ni][half * 2 + 1] + bias[cg + 1]);
            }
        }
    }
}

// ---------------- u = sigmoid(t @ wu^T + bu) ---------------------------------
__global__ void u_kernel(const float* __restrict__ wu, const float* __restrict__ bu,
                         float* __restrict__ dout_u) {
    int i = blockIdx.x * 8 + (threadIdx.x >> 5);
    int lane = threadIdx.x & 31;
    const float* t = g_t + (size_t)i * CCH;
    float s = 0.f;
    #pragma unroll
    for (int j = 0; j < 8; j++) s += t[lane + j * 32] * wu[lane + j * 32];
    #pragma unroll
    for (int o = 16; o; o >>= 1) s += __shfl_down_sync(~0u, s, o);
    if (lane == 0) {
        float uu = 1.f / (1.f + expf(-(s + bu[0])));
        g_u[i] = uu; dout_u[i] = uu;
    }
}

// ---------------- warp-specialized flash (fp16 QK, bf16 PV) ------------------
__global__ __launch_bounds__(256, 1)
void flash4(const __half* __restrict__ qkh, const unsigned* __restrict__ vp,
            float* __restrict__ o) {
    extern __shared__ float dsm[];
    unsigned* dsu = (unsigned*)dsm;
    uint32_t sb = smem_u32(dsm);
    int b = blockIdx.y, q0 = blockIdx.x * BM;
    int tid = threadIdx.x, lane = tid & 31, warp = tid >> 5;
    int g = lane >> 2, t4 = lane & 3;
    size_t tokb = (size_t)b * BHW;
    const __half* Qg = qkh + (tokb + q0) * 512;
    const __half* Kg = qkh + tokb * 512 + 256;
    const unsigned* Vg = vp + (size_t)b * 2048 * 256;

    // stage Q fp16 [64][264h]
    for (int i = tid; i < 2048; i += 256) {
        int r = i >> 5, c8 = i & 31;
        cp16(sb + QSTGW * 4 + r * 528 + c8 * 16, Qg + (size_t)r * 512 + c8 * 8);
    }
    CP_COMMIT; CP_WAIT0; __syncthreads();

    float rp[128];   // QK warps: 64 packed Q frags. PV warps: 128 accO.
    if (warp < 4) {
        int r0 = warp * 16 + g;
        const __half* q = (const __half*)(dsm + QSTGW);
        #pragma unroll
        for (int k16 = 0; k16 < 16; k16++) {
            rp[k16*4+0] = __uint_as_float(*(const unsigned*)&q[r0 * 264 + k16*16 + t4*2]);
            rp[k16*4+1] = __uint_as_float(*(const unsigned*)&q[(r0+8) * 264 + k16*16 + t4*2]);
            rp[k16*4+2] = __uint_as_float(*(const unsigned*)&q[r0 * 264 + k16*16 + 8 + t4*2]);
            rp[k16*4+3] = __uint_as_float(*(const unsigned*)&q[(r0+8) * 264 + k16*16 + 8 + t4*2]);
        }
    } else {
        #pragma unroll
        for (int j = 0; j < 128; j++) rp[j] = 0.f;
    }
    __syncthreads();

    for (int i = tid; i < 1024; i += 256) {     // K(0) fp16 [32][264h]
        int r = i >> 5, c8 = i & 31;
        cp16(sb + KW(0) * 4 + r * 528 + c8 * 16, Kg + (size_t)r * 512 + c8 * 8);
    }
    for (int i = tid; i < 1024; i += 256) {     // V(0)
        int r = i >> 6, c4 = (i & 63) * 4;
        cp16(sb + (VW(0) + r * 264 + c4) * 4, Vg + (size_t)r * 256 + c4);
    }
    CP_COMMIT;

    int w = warp - 4, wm = w & 1, wn = w >> 1;
    float lac[4] = {0.f, 0.f, 0.f, 0.f};

    for (int it = 0; it <= FITERS; ++it) {
        CP_WAIT0; __syncthreads();
        if (it + 1 < FITERS) {
            const __half* kn = Kg + (size_t)(it + 1) * BN * 512;
            const unsigned* vn = Vg + (size_t)(it + 1) * 16 * 256;
            int kb4 = KW((it + 1) & 1) * 4, vd = VW((it + 1) % 3);
            for (int i = tid; i < 1024; i += 256) {
                int r = i >> 5, c8 = i & 31;
                cp16(sb + kb4 + r * 528 + c8 * 16, kn + (size_t)r * 512 + c8 * 8);
            }
            for (int i = tid; i < 1024; i += 256) {
                int r = i >> 6, c4 = (i & 63) * 4;
                cp16(sb + (vd + r * 264 + c4) * 4, vn + (size_t)r * 256 + c4);
            }
            CP_COMMIT;
        }
        if (warp < 4) {
            if (it < FITERS) {          // QK fp16: raw S
                const __half* kb = (const __half*)(dsm + KW(it & 1));
                float sacc[4][4];
                #pragma unroll
                for (int ni = 0; ni < 4; ni++)
                    #pragma unroll
                    for (int e = 0; e < 4; e++) sacc[ni][e] = 0.f;
                #pragma unroll
                for (int k16 = 0; k16 < 16; k16++) {
                    unsigned af[4] = { fu(rp[k16*4]), fu(rp[k16*4+1]), fu(rp[k16*4+2]), fu(rp[k16*4+3]) };
                    #pragma unroll
                    for (int ni = 0; ni < 4; ni++) {
                        int c = ni * 8 + g;
                        unsigned b0 = *(const unsigned*)&kb[c * 264 + k16*16 + t4*2];
                        unsigned b1 = *(const unsigned*)&kb[c * 264 + k16*16 + 8 + t4*2];
                        mma_f16(sacc[ni], af, b0, b1);
                    }
                }
                float* S = dsm + SW(it & 1);
                int r0 = warp * 16 + g;
                #pragma unroll
                for (int ni = 0; ni < 4; ni++) {
                    *(float2*)&S[r0 * 36 + ni*8 + t4*2]       = make_float2(sacc[ni][0], sacc[ni][1]);
                    *(float2*)&S[(r0 + 8) * 36 + ni*8 + t4*2] = make_float2(sacc[ni][2], sacc[ni][3]);
                }
            }
        } else if (it >= 1) {            // PV: exp + bf16 mma
            int pit = it - 1;
            const float* S = dsm + SW(pit & 1);
            const unsigned* V = dsu + VW(pit % 3);
            unsigned af[2][2][4];
            #pragma unroll
            for (int mi = 0; mi < 2; mi++) {
                int r0 = wm * 32 + mi * 16 + g;
                #pragma unroll
                for (int k16 = 0; k16 < 2; k16++) {
                    float2 v00 = *(const float2*)&S[r0 * 36 + k16*16 + t4*2];
                    float2 v10 = *(const float2*)&S[(r0+8) * 36 + k16*16 + t4*2];
                    float2 v01 = *(const float2*)&S[r0 * 36 + k16*16 + 8 + t4*2];
                    float2 v11 = *(const float2*)&S[(r0+8) * 36 + k16*16 + 8 + t4*2];
                    float e0x = __expf(v00.x), e0y = __expf(v00.y);
                    float e1x = __expf(v10.x), e1y = __expf(v10.y);
                    float e2x = __expf(v01.x), e2y = __expf(v01.y);
                    float e3x = __expf(v11.x), e3y = __expf(v11.y);
                    if (wn == 0) {
                        lac[mi*2+0] += e0x + e0y + e2x + e2y;
                        lac[mi*2+1] += e1x + e1y + e3x + e3y;
                    }
                    af[mi][k16][0] = pack_bf(e0x, e0y);
                    af[mi][k16][1] = pack_bf(e1x, e1y);
                    af[mi][k16][2] = pack_bf(e2x, e2y);
                    af[mi][k16][3] = pack_bf(e3x, e3y);
                }
            }
            #pragma unroll
            for (int k16 = 0; k16 < 2; k16++) {
                #pragma unroll
                for (int ni = 0; ni < 16; ni++) {
                    int c = wn * 128 + ni * 8 + g;
                    unsigned b0 = V[(k16*8 + t4) * 264 + c];
                    unsigned b1 = V[(k16*8 + 4 + t4) * 264 + c];
                    mma_bf16(&rp[ni*4],      af[0][k16], b0, b1);
                    mma_bf16(&rp[64 + ni*4], af[1][k16], b0, b1);
                }
            }
        }
    }

    if (warp >= 4 && wn == 0) {
        #pragma unroll
        for (int j = 0; j < 4; j++) {
            lac[j] += __shfl_xor_sync(~0u, lac[j], 1);
            lac[j] += __shfl_xor_sync(~0u, lac[j], 2);
        }
        if (t4 == 0) {
            dsm[SLW + wm*32 + g]      = lac[0];
            dsm[SLW + wm*32 + g + 8]  = lac[1];
            dsm[SLW + wm*32 + g + 16] = lac[2];
            dsm[SLW + wm*32 + g + 24] = lac[3];
        }
    }
    __syncthreads();
    if (warp >= 4) {
        #pragma unroll
        for (int mi = 0; mi < 2; mi++) {
            int r = wm * 32 + mi * 16 + g;
            float i0 = 1.f / dsm[SLW + r];
            float i1 = 1.f / dsm[SLW + r + 8];
            float* o0 = o + (tokb + q0 + r) * 256;
            float* o1 = o + (tokb + q0 + r + 8) * 256;
            #pragma unroll
            for (int ni = 0; ni < 16; ni++) {
                int cc = wn * 128 + ni * 8 + t4 * 2;
                float* a = &rp[mi * 64 + ni * 4];
                *(float2*)&o0[cc] = make_float2(a[0] * i0, a[1] * i0);
                *(float2*)&o1[cc] = make_float2(a[2] * i1, a[3] * i1);
            }
        }
    }
}

// ---------------- final: out = x + y^T ---------------------------------------
__global__ void final_out(const float* __restrict__ x, float* __restrict__ out) {
    __shared__ float tile[32][33];
    int b = blockIdx.z, c0 = blockIdx.y * 32, s0 = blockIdx.x * 32;
    int tx = threadIdx.x, ty = threadIdx.y;
    for (int i = ty; i < 32; i += 8)
        tile[i][tx] = g_y[((size_t)(b * BHW + s0 + i)) * CCH + c0 + tx];
    __syncthreads();
    for (int i = ty; i < 32; i += 8) {
        size_t idx = ((size_t)(b * CCH + c0 + i)) * BHW + s0 + tx;
        out[idx] = x[idx] + tile[tx][i];
    }
}

// ---------------- launch -----------------------------------------------------
extern "C" void kernel_launch(void* const* d_in, const int* in_sizes, int n_in,
                              void* d_out, int out_size) {
    (void)in_sizes; (void)n_in; (void)out_size;
    const float* x     = (const float*)d_in[0];
    const float* gamma = (const float*)d_in[1];
    const float* beta  = (const float*)d_in[2];
    const float* wq = (const float*)d_in[3],  *bq = (const float*)d_in[4];
    const float* wk = (const float*)d_in[5],  *bk = (const float*)d_in[6];
    const float* wv = (const float*)d_in[7],  *bv = (const float*)d_in[8];
    const float* wu = (const float*)d_in[9],  *bu = (const float*)d_in[10];
    const float* wp = (const float*)d_in[11], *bp = (const float*)d_in[12];
    float* out = (float*)d_out;

    float *pt, *po, *py, *pu;
    __half* pqk;
    unsigned* pvp;
    cudaGetSymbolAddress((void**)&pt,  g_t);
    cudaGetSymbolAddress((void**)&pqk, g_qkh);
    cudaGetSymbolAddress((void**)&pvp, g_vp);
    cudaGetSymbolAddress((void**)&po,  g_o);
    cudaGetSymbolAddress((void**)&py,  g_y);
    cudaGetSymbolAddress((void**)&pu,  g_u);

    cudaFuncSetAttribute(flash4, cudaFuncAttributeMaxDynamicSharedMemorySize, FSMEM);

    gn_stats<<<NBAT * NGRP, 256>>>(x);
    gn_apply<<<dim3(BHW / 32, CCH / 32, NBAT), dim3(32, 8)>>>(x, gamma, beta);
    u_kernel<<<NTOK / 8, 256>>>(wu, bu, out + OUT_MAIN);
    gemm_qkv<<<dim3(6, 128), 256>>>(pt, wq, wk, wv, bq, bk, bv, pqk, pvp, pu);
    flash4<<<dim3(BHW / BM, NBAT), 256, FSMEM>>>(pqk, pvp, po);
    gemm_proj<<<dim3(2, 128), 256>>>(po, wp, bp, py);
    final_out<<<dim3(BHW / 32, CCH / 32, NBAT), dim3(32, 8)>>>(x, out);
}

// round 11
// speedup vs baseline: 2.0259x; 1.0808x over previous
#include <cuda_runtime.h>
#include <cuda_bf16.h>
#include <cuda_fp16.h>
#include <stdint.h>

#define BHW   4096
#define CCH   256
#define NBAT  4
#define NTOK  16384
#define NGRP  32
#define GELEMS (8*BHW)
#define OUT_MAIN ((size_t)NBAT*CCH*BHW)

#define BM 64
#define BN 32
#define FITERS 128
// flash smem WORD offsets
#define KW(i)  ((i)*4224)
#define VW(j)  (8448 + (j)*4224)
#define QSTGW  8448
#define SW(p)  (21120 + (p)*2304)
#define SLW    25728
#define FSMEM  (25792*4)

__device__ __half   g_th[(size_t)NTOK*CCH];     // normed tokens fp16
__device__ __half   g_qkh[(size_t)NTOK*512];    // q | k*u/16 fp16
__device__ unsigned g_vp[(size_t)(NTOK/2)*256]; // v bf16 token-pair packed
__device__ __half   g_oh[(size_t)NTOK*CCH];     // attn out fp16
__device__ __half   g_wh[(size_t)1024*256];     // wq|wk|wv|wp fp16
__device__ float    g_u[NTOK];
__device__ float    g_mu[NBAT*NGRP];
__device__ float    g_rs[NBAT*NGRP];

__device__ __forceinline__ unsigned fu(float f) { return __float_as_uint(f); }
__device__ __forceinline__ void mma_f16(float* c, const unsigned* a, unsigned b0, unsigned b1) {
    asm volatile("mma.sync.aligned.m16n8k16.row.col.f32.f16.f16.f32 "
                 "{%0,%1,%2,%3}, {%4,%5,%6,%7}, {%8,%9}, {%0,%1,%2,%3};"
                 : "+f"(c[0]), "+f"(c[1]), "+f"(c[2]), "+f"(c[3])
                 : "r"(a[0]), "r"(a[1]), "r"(a[2]), "r"(a[3]), "r"(b0), "r"(b1));
}
__device__ __forceinline__ void mma_bf16(float* c, const unsigned* a, unsigned b0, unsigned b1) {
    asm volatile("mma.sync.aligned.m16n8k16.row.col.f32.bf16.bf16.f32 "
                 "{%0,%1,%2,%3}, {%4,%5,%6,%7}, {%8,%9}, {%0,%1,%2,%3};"
                 : "+f"(c[0]), "+f"(c[1]), "+f"(c[2]), "+f"(c[3])
                 : "r"(a[0]), "r"(a[1]), "r"(a[2]), "r"(a[3]), "r"(b0), "r"(b1));
}
__device__ __forceinline__ uint32_t smem_u32(const void* p) {
    uint32_t a;
    asm("{ .reg .u64 t; cvta.to.shared.u64 t, %1; cvt.u32.u64 %0, t; }" : "=r"(a) : "l"(p));
    return a;
}
__device__ __forceinline__ void cp16(uint32_t saddr, const void* g) {
    asm volatile("cp.async.cg.shared.global [%0], [%1], 16;" :: "r"(saddr), "l"(g));
}
#define CP_COMMIT asm volatile("cp.async.commit_group;" ::: "memory")
#define CP_WAIT0  asm volatile("cp.async.wait_group 0;" ::: "memory")
__device__ __forceinline__ unsigned pack_bf(float lo, float hi) {
    unsigned r;
    asm("cvt.rn.bf16x2.f32 %0, %1, %2;" : "=r"(r) : "f"(hi), "f"(lo));
    return r;
}

// ---------------- GroupNorm --------------------------------------------------
__global__ void gn_stats(const float* __restrict__ x) {
    int bg = blockIdx.x;
    const float4* p = (const float4*)(x + (size_t)bg * GELEMS);
    float s = 0.f, ss = 0.f;
    for (int i = threadIdx.x; i < GELEMS/4; i += blockDim.x) {
        float4 v = p[i];
        s += v.x + v.y + v.z + v.w;
        ss += v.x*v.x + v.y*v.y + v.z*v.z + v.w*v.w;
    }
    __shared__ float rs[8], rss[8];
    #pragma unroll
    for (int o = 16; o; o >>= 1) { s += __shfl_down_sync(~0u, s, o); ss += __shfl_down_sync(~0u, ss, o); }
    if ((threadIdx.x & 31) == 0) { rs[threadIdx.x >> 5] = s; rss[threadIdx.x >> 5] = ss; }
    __syncthreads();
    if (threadIdx.x < 32) {
        s  = (threadIdx.x < 8) ? rs[threadIdx.x]  : 0.f;
        ss = (threadIdx.x < 8) ? rss[threadIdx.x] : 0.f;
        #pragma unroll
        for (int o = 4; o; o >>= 1) { s += __shfl_down_sync(~0u, s, o); ss += __shfl_down_sync(~0u, ss, o); }
        if (threadIdx.x == 0) {
            float mu = s / (float)GELEMS;
            float var = ss / (float)GELEMS - mu * mu;
            g_mu[bg] = mu; g_rs[bg] = rsqrtf(var + 1e-6f);
        }
    }
}

__global__ void gn_apply(const float* __restrict__ x, const float* __restrict__ gamma,
                         const float* __restrict__ beta) {
    __shared__ float tile[32][33];
    int b = blockIdx.z, c0 = blockIdx.y * 32, s0 = blockIdx.x * 32;
    int tx = threadIdx.x, ty = threadIdx.y;
    for (int i = ty; i < 32; i += 8) {
        int c = c0 + i, bg = b * NGRP + (c >> 3);
        float v = x[((size_t)(b * CCH + c)) * BHW + s0 + tx];
        tile[i][tx] = (v - g_mu[bg]) * g_rs[bg] * gamma[c] + beta[c];
    }
    __syncthreads();
    for (int i = ty; i < 32; i += 8)
        g_th[((size_t)(b * BHW + s0 + i)) * CCH + c0 + tx] = __float2half(tile[tx][i]);
}

// ---------------- weight pack to fp16 ----------------------------------------
__global__ void w_pack(const float* __restrict__ wq, const float* __restrict__ wk,
                       const float* __restrict__ wv, const float* __restrict__ wp) {
    int r = blockIdx.x, tid = threadIdx.x;
    const float* w = (r < 256) ? wq : (r < 512) ? wk : (r < 768) ? wv : wp;
    g_wh[(size_t)r * 256 + tid] = __float2half(w[(size_t)(r & 255) * 256 + tid]);
}

// ---------------- fp16 gemm core (K=256) -------------------------------------
__device__ __forceinline__ void gemm_core_h(const __half* A, const __half* B, int m0,
                                            __half* As, __half* Bs, float acc[2][8][4]) {
    const int tid = threadIdx.x, lane = tid & 31, warp = tid >> 5;
    const int wm = warp >> 1, wn = warp & 1, g = lane >> 2, t4 = lane & 3;
    #pragma unroll
    for (int mi = 0; mi < 2; mi++)
        #pragma unroll
        for (int ni = 0; ni < 8; ni++)
            #pragma unroll
            for (int e = 0; e < 4; e++) acc[mi][ni][e] = 0.f;
    for (int kc = 0; kc < 256; kc += 32) {
        #pragma unroll
        for (int it = 0; it < 2; it++) {
            int idx = tid + it * 256, row = idx >> 2, seg = idx & 3;
            *(float4*)(As + row * 40 + seg * 8) =
                *(const float4*)(A + (size_t)(m0 + row) * 256 + kc + seg * 8);
            *(float4*)(Bs + row * 40 + seg * 8) =
                *(const float4*)(B + (size_t)row * 256 + kc + seg * 8);
        }
        __syncthreads();
        #pragma unroll
        for (int k16 = 0; k16 < 2; k16++) {
            unsigned af[2][4];
            #pragma unroll
            for (int mi = 0; mi < 2; mi++) {
                int r = wm * 32 + mi * 16 + g;
                af[mi][0] = *(unsigned*)&As[r * 40 + k16*16 + t4*2];
                af[mi][1] = *(unsigned*)&As[(r + 8) * 40 + k16*16 + t4*2];
                af[mi][2] = *(unsigned*)&As[r * 40 + k16*16 + 8 + t4*2];
                af[mi][3] = *(unsigned*)&As[(r + 8) * 40 + k16*16 + 8 + t4*2];
            }
            #pragma unroll
            for (int ni = 0; ni < 8; ni++) {
                int cc = wn * 64 + ni * 8 + g;
                unsigned b0 = *(unsigned*)&Bs[cc * 40 + k16*16 + t4*2];
                unsigned b1 = *(unsigned*)&Bs[cc * 40 + k16*16 + 8 + t4*2];
                mma_f16(acc[0][ni], af[0], b0, b1);
                mma_f16(acc[1][ni], af[1], b0, b1);
            }
        }
        __syncthreads();
    }
}

// qkv: q,k -> fp16 (k scaled u/16); v -> bf16 token-pair packed
__global__ __launch_bounds__(256, 2)
void gemm_qkv(const float* __restrict__ bq, const float* __restrict__ bk,
              const float* __restrict__ bv) {
    const int n0 = blockIdx.x * 128, m0 = blockIdx.y * 128;
    const float* Bi = (n0 < 256) ? bq : (n0 < 512) ? bk : bv;
    __shared__ __align__(16) __half As[128 * 40];
    __shared__ __align__(16) __half Bs[128 * 40];
    float acc[2][8][4];
    gemm_core_h(g_th, g_wh + (size_t)n0 * 256, m0, As, Bs, acc);
    const int lane = threadIdx.x & 31, warp = threadIdx.x >> 5;
    const int wm = warp >> 1, wn = warp & 1, g = lane >> 2, t4 = lane & 3;
    #pragma unroll
    for (int mi = 0; mi < 2; mi++) {
        int rbase = m0 + wm * 32 + mi * 16 + g;
        #pragma unroll
        for (int ni = 0; ni < 8; ni++) {
            int cl = wn * 64 + ni * 8 + t4 * 2, cg = n0 + cl;
            #pragma unroll
            for (int half = 0; half < 2; half++) {
                int rr = rbase + half * 8;
                float v0 = acc[mi][ni][half * 2 + 0] + Bi[(n0 & 255) + cl];
                float v1 = acc[mi][ni][half * 2 + 1] + Bi[(n0 & 255) + cl + 1];
                if (cg < 512) {
                    if (cg >= 256) { float us = g_u[rr] * 0.0625f; v0 *= us; v1 *= us; }
                    *(__half2*)&g_qkh[(size_t)rr * 512 + cg] = __floats2half2_rn(v0, v1);
                } else {
                    int c2 = cg - 512, t2 = rr >> 1, par = rr & 1;
                    __nv_bfloat16* vb = (__nv_bfloat16*)g_vp;
                    vb[((size_t)t2 * 256 + c2) * 2 + par]     = __float2bfloat16(v0);
                    vb[((size_t)t2 * 256 + c2 + 1) * 2 + par] = __float2bfloat16(v1);
                }
            }
        }
    }
}

// proj transposed: out[b][c][s] = x + Wp @ O^T + bp
__global__ __launch_bounds__(256, 2)
void gemm_proj_t(const float* __restrict__ x, const float* __restrict__ bias,
                 float* __restrict__ out) {
    const int n0 = blockIdx.x * 128;   // token tile
    const int m0 = blockIdx.y * 128;   // channel tile
    __shared__ __align__(16) __half As[128 * 40];
    __shared__ __align__(16) __half Bs[128 * 40];
    float acc[2][8][4];
    gemm_core_h(g_wh + (size_t)768 * 256, g_oh + (size_t)n0 * 256, m0, As, Bs, acc);
    const int lane = threadIdx.x & 31, warp = threadIdx.x >> 5;
    const int wm = warp >> 1, wn = warp & 1, g = lane >> 2, t4 = lane & 3;
    #pragma unroll
    for (int mi = 0; mi < 2; mi++) {
        int chb = m0 + wm * 32 + mi * 16 + g;
        #pragma unroll
        for (int ni = 0; ni < 8; ni++) {
            int tok = n0 + wn * 64 + ni * 8 + t4 * 2;
            int bb = tok >> 12, s = tok & 4095;
            #pragma unroll
            for (int half = 0; half < 2; half++) {
                int ch = chb + half * 8;
                size_t idx = ((size_t)(bb * CCH + ch)) * BHW + s;
                float2 xv = *(const float2*)(x + idx);
                *(float2*)(out + idx) =
                    make_float2(acc[mi][ni][half * 2 + 0] + bias[ch] + xv.x,
                                acc[mi][ni][half * 2 + 1] + bias[ch] + xv.y);
            }
        }
    }
}

// ---------------- u = sigmoid(t @ wu^T + bu) ---------------------------------
__global__ void u_kernel(const float* __restrict__ wu, const float* __restrict__ bu,
                         float* __restrict__ dout_u) {
    int i = blockIdx.x * 8 + (threadIdx.x >> 5);
    int lane = threadIdx.x & 31;
    const __half2* t2 = (const __half2*)(g_th + (size_t)i * CCH);
    float s = 0.f;
    #pragma unroll
    for (int j = 0; j < 4; j++) {
        float2 f = __half22float2(t2[lane + j * 32]);
        int c = (lane + j * 32) * 2;
        s += f.x * wu[c] + f.y * wu[c + 1];
    }
    #pragma unroll
    for (int o = 16; o; o >>= 1) s += __shfl_down_sync(~0u, s, o);
    if (lane == 0) {
        float uu = 1.f / (1.f + expf(-(s + bu[0])));
        g_u[i] = uu; dout_u[i] = uu;
    }
}

// ---------------- warp-specialized flash (fp16 QK, bf16 PV) ------------------
__global__ __launch_bounds__(256, 1)
void flash4(float* __restrict__ unused) {
    extern __shared__ float dsm[];
    unsigned* dsu = (unsigned*)dsm;
    uint32_t sb = smem_u32(dsm);
    int b = blockIdx.y, q0 = blockIdx.x * BM;
    int tid = threadIdx.x, lane = tid & 31, warp = tid >> 5;
    int g = lane >> 2, t4 = lane & 3;
    size_t tokb = (size_t)b * BHW;
    const __half* Qg = g_qkh + (tokb + q0) * 512;
    const __half* Kg = g_qkh + tokb * 512 + 256;
    const unsigned* Vg = g_vp + (size_t)b * 2048 * 256;

    for (int i = tid; i < 2048; i += 256) {
        int r = i >> 5, c8 = i & 31;
        cp16(sb + QSTGW * 4 + r * 528 + c8 * 16, Qg + (size_t)r * 512 + c8 * 8);
    }
    CP_COMMIT; CP_WAIT0; __syncthreads();

    float rp[128];
    if (warp < 4) {
        int r0 = warp * 16 + g;
        const __half* q = (const __half*)(dsm + QSTGW);
        #pragma unroll
        for (int k16 = 0; k16 < 16; k16++) {
            rp[k16*4+0] = __uint_as_float(*(const unsigned*)&q[r0 * 264 + k16*16 + t4*2]);
            rp[k16*4+1] = __uint_as_float(*(const unsigned*)&q[(r0+8) * 264 + k16*16 + t4*2]);
            rp[k16*4+2] = __uint_as_float(*(const unsigned*)&q[r0 * 264 + k16*16 + 8 + t4*2]);
            rp[k16*4+3] = __uint_as_float(*(const unsigned*)&q[(r0+8) * 264 + k16*16 + 8 + t4*2]);
        }
    } else {
        #pragma unroll
        for (int j = 0; j < 128; j++) rp[j] = 0.f;
    }
    __syncthreads();

    for (int i = tid; i < 1024; i += 256) {
        int r = i >> 5, c8 = i & 31;
        cp16(sb + KW(0) * 4 + r * 528 + c8 * 16, Kg + (size_t)r * 512 + c8 * 8);
    }
    for (int i = tid; i < 1024; i += 256) {
        int r = i >> 6, c4 = (i & 63) * 4;
        cp16(sb + (VW(0) + r * 264 + c4) * 4, Vg + (size_t)r * 256 + c4);
    }
    CP_COMMIT;

    int w = warp - 4, wm = w & 1, wn = w >> 1;
    float lac[4] = {0.f, 0.f, 0.f, 0.f};

    for (int it = 0; it <= FITERS; ++it) {
        CP_WAIT0; __syncthreads();
        if (it + 1 < FITERS) {
            const __half* kn = Kg + (size_t)(it + 1) * BN * 512;
            const unsigned* vn = Vg + (size_t)(it + 1) * 16 * 256;
            int kb4 = KW((it + 1) & 1) * 4, vd = VW((it + 1) % 3);
            for (int i = tid; i < 1024; i += 256) {
                int r = i >> 5, c8 = i & 31;
                cp16(sb + kb4 + r * 528 + c8 * 16, kn + (size_t)r * 512 + c8 * 8);
            }
            for (int i = tid; i < 1024; i += 256) {
                int r = i >> 6, c4 = (i & 63) * 4;
                cp16(sb + (vd + r * 264 + c4) * 4, vn + (size_t)r * 256 + c4);
            }
            CP_COMMIT;
        }
        if (warp < 4) {
            if (it < FITERS) {
                const __half* kb = (const __half*)(dsm + KW(it & 1));
                float sacc[4][4];
                #pragma unroll
                for (int ni = 0; ni < 4; ni++)
                    #pragma unroll
                    for (int e = 0; e < 4; e++) sacc[ni][e] = 0.f;
                #pragma unroll
                for (int k16 = 0; k16 < 16; k16++) {
                    unsigned af[4] = { fu(rp[k16*4]), fu(rp[k16*4+1]), fu(rp[k16*4+2]), fu(rp[k16*4+3]) };
                    #pragma unroll
                    for (int ni = 0; ni < 4; ni++) {
                        int c = ni * 8 + g;
                        unsigned b0 = *(const unsigned*)&kb[c * 264 + k16*16 + t4*2];
                        unsigned b1 = *(const unsigned*)&kb[c * 264 + k16*16 + 8 + t4*2];
                        mma_f16(sacc[ni], af, b0, b1);
                    }
                }
                float* S = dsm + SW(it & 1);
                int r0 = warp * 16 + g;
                #pragma unroll
                for (int ni = 0; ni < 4; ni++) {
                    *(float2*)&S[r0 * 36 + ni*8 + t4*2]       = make_float2(sacc[ni][0], sacc[ni][1]);
                    *(float2*)&S[(r0 + 8) * 36 + ni*8 + t4*2] = make_float2(sacc[ni][2], sacc[ni][3]);
                }
            }
        } else if (it >= 1) {
            int pit = it - 1;
            const float* S = dsm + SW(pit & 1);
            const unsigned* V = dsu + VW(pit % 3);
            unsigned af[2][2][4];
            #pragma unroll
            for (int mi = 0; mi < 2; mi++) {
                int r0 = wm * 32 + mi * 16 + g;
                #pragma unroll
                for (int k16 = 0; k16 < 2; k16++) {
                    float2 v00 = *(const float2*)&S[r0 * 36 + k16*16 + t4*2];
                    float2 v10 = *(const float2*)&S[(r0+8) * 36 + k16*16 + t4*2];
                    float2 v01 = *(const float2*)&S[r0 * 36 + k16*16 + 8 + t4*2];
                    float2 v11 = *(const float2*)&S[(r0+8) * 36 + k16*16 + 8 + t4*2];
                    float e0x = __expf(v00.x), e0y = __expf(v00.y);
                    float e1x = __expf(v10.x), e1y = __expf(v10.y);
                    float e2x = __expf(v01.x), e2y = __expf(v01.y);
                    float e3x = __expf(v11.x), e3y = __expf(v11.y);
                    if (wn == 0) {
                        lac[mi*2+0] += e0x + e0y + e2x + e2y;
                        lac[mi*2+1] += e1x + e1y + e3x + e3y;
                    }
                    af[mi][k16][0] = pack_bf(e0x, e0y);
                    af[mi][k16][1] = pack_bf(e1x, e1y);
                    af[mi][k16][2] = pack_bf(e2x, e2y);
                    af[mi][k16][3] = pack_bf(e3x, e3y);
                }
            }
            #pragma unroll
            for (int k16 = 0; k16 < 2; k16++) {
                #pragma unroll
                for (int ni = 0; ni < 16; ni++) {
                    int c = wn * 128 + ni * 8 + g;
                    unsigned b0 = V[(k16*8 + t4) * 264 + c];
                    unsigned b1 = V[(k16*8 + 4 + t4) * 264 + c];
                    mma_bf16(&rp[ni*4],      af[0][k16], b0, b1);
                    mma_bf16(&rp[64 + ni*4], af[1][k16], b0, b1);
                }
            }
        }
    }

    if (warp >= 4 && wn == 0) {
        #pragma unroll
        for (int j = 0; j < 4; j++) {
            lac[j] += __shfl_xor_sync(~0u, lac[j], 1);
            lac[j] += __shfl_xor_sync(~0u, lac[j], 2);
        }
        if (t4 == 0) {
            dsm[SLW + wm*32 + g]      = lac[0];
            dsm[SLW + wm*32 + g + 8]  = lac[1];
            dsm[SLW + wm*32 + g + 16] = lac[2];
            dsm[SLW + wm*32 + g + 24] = lac[3];
        }
    }
    __syncthreads();
    if (warp >= 4) {
        #pragma unroll
        for (int mi = 0; mi < 2; mi++) {
            int r = wm * 32 + mi * 16 + g;
            float i0 = 1.f / dsm[SLW + r];
            float i1 = 1.f / dsm[SLW + r + 8];
            __half* o0 = g_oh + (tokb + q0 + r) * 256;
            __half* o1 = g_oh + (tokb + q0 + r + 8) * 256;
            #pragma unroll
            for (int ni = 0; ni < 16; ni++) {
                int cc = wn * 128 + ni * 8 + t4 * 2;
                float* a = &rp[mi * 64 + ni * 4];
                *(__half2*)&o0[cc] = __floats2half2_rn(a[0] * i0, a[1] * i0);
                *(__half2*)&o1[cc] = __floats2half2_rn(a[2] * i1, a[3] * i1);
            }
        }
    }
    (void)unused;
}

// ---------------- launch -----------------------------------------------------
extern "C" void kernel_launch(void* const* d_in, const int* in_sizes, int n_in,
                              void* d_out, int out_size) {
    (void)in_sizes; (void)n_in; (void)out_size;
    const float* x     = (const float*)d_in[0];
    const float* gamma = (const float*)d_in[1];
    const float* beta  = (const float*)d_in[2];
    const float* wq = (const float*)d_in[3],  *bq = (const float*)d_in[4];
    const float* wk = (const float*)d_in[5],  *bk = (const float*)d_in[6];
    const float* wv = (const float*)d_in[7],  *bv = (const float*)d_in[8];
    const float* wu = (const float*)d_in[9],  *bu = (const float*)d_in[10];
    const float* wp = (const float*)d_in[11], *bp = (const float*)d_in[12];
    float* out = (float*)d_out;

    cudaFuncSetAttribute(flash4, cudaFuncAttributeMaxDynamicSharedMemorySize, FSMEM);

    gn_stats<<<NBAT * NGRP, 256>>>(x);
    gn_apply<<<dim3(BHW / 32, CCH / 32, NBAT), dim3(32, 8)>>>(x, gamma, beta);
    u_kernel<<<NTOK / 8, 256>>>(wu, bu, out + OUT_MAIN);
    w_pack<<<1024, 256>>>(wq, wk, wv, wp);
    gemm_qkv<<<dim3(6, 128), 256>>>(bq, bk, bv);
    flash4<<<dim3(BHW / BM, NBAT), 256, FSMEM>>>(out);
    gemm_proj_t<<<dim3(128, 2), 256>>>(x, bp, out);
}